// round 1
// baseline (speedup 1.0000x reference)
#include <cuda_runtime.h>
#include <cuda_bf16.h>
#include <cstdint>

// ---------------------------------------------------------------------------
// GQA layer: Q/K/V projections -> causal flash attention (GQA, 32 heads,
// group=8, repeats=4) -> output projection.  All fp32 baseline.
// ---------------------------------------------------------------------------

#define S_LEN   2048
#define D_MODEL 2048
#define H_Q     32
#define H_KV    8
#define DK      64
#define DV      64
#define KV_W    (H_KV * DK)   // 512

// Scratch (no cudaMalloc allowed) — 40 MB total.
__device__ float g_q[S_LEN * D_MODEL];      // [S, H*64]
__device__ float g_k[S_LEN * KV_W];         // [S, G*64]
__device__ float g_v[S_LEN * KV_W];         // [S, G*64]
__device__ float g_attn[S_LEN * D_MODEL];   // [S, H*64]

// ---------------------------------------------------------------------------
// SGEMM: C[M,N] = A[M,K] @ B[K,N] + bias[N].  Row-major. M,N % 128 == 0,
// K % 8 == 0.  BM=BN=128, BK=8, 256 threads, 8x8 micro-tile per thread.
// ---------------------------------------------------------------------------
__global__ __launch_bounds__(256)
void sgemm_bias(const float* __restrict__ A, const float* __restrict__ B,
                const float* __restrict__ bias, float* __restrict__ C,
                int M, int N, int K)
{
    __shared__ float As[8][128];
    __shared__ float Bs[8][128];

    const int bx  = blockIdx.x;        // N tile
    const int by  = blockIdx.y;        // M tile
    const int tid = threadIdx.x;
    const int tx  = tid & 15;          // 0..15
    const int ty  = tid >> 4;          // 0..15

    float acc[8][8];
    #pragma unroll
    for (int i = 0; i < 8; i++)
        #pragma unroll
        for (int j = 0; j < 8; j++)
            acc[i][j] = 0.f;

    // load mapping
    const int aRow = tid >> 1;         // 0..127
    const int aCol = (tid & 1) * 4;    // 0 or 4
    const int bRow = tid >> 5;         // 0..7
    const int bCol = (tid & 31) * 4;   // 0..124

    const float* Aptr = A + (size_t)(by * 128 + aRow) * K + aCol;
    const float* Bptr = B + (size_t)bRow * N + bx * 128 + bCol;

    for (int k0 = 0; k0 < K; k0 += 8) {
        float4 a = *(const float4*)(Aptr + k0);
        float4 b = *(const float4*)(Bptr + (size_t)k0 * N);

        As[aCol + 0][aRow] = a.x;
        As[aCol + 1][aRow] = a.y;
        As[aCol + 2][aRow] = a.z;
        As[aCol + 3][aRow] = a.w;
        *(float4*)(&Bs[bRow][bCol]) = b;
        __syncthreads();

        #pragma unroll
        for (int k = 0; k < 8; k++) {
            float ar[8], br[8];
            #pragma unroll
            for (int i = 0; i < 8; i += 4) {
                float4 t = *(const float4*)(&As[k][ty * 8 + i]);
                ar[i] = t.x; ar[i + 1] = t.y; ar[i + 2] = t.z; ar[i + 3] = t.w;
            }
            #pragma unroll
            for (int j = 0; j < 8; j += 4) {
                float4 t = *(const float4*)(&Bs[k][tx * 8 + j]);
                br[j] = t.x; br[j + 1] = t.y; br[j + 2] = t.z; br[j + 3] = t.w;
            }
            #pragma unroll
            for (int i = 0; i < 8; i++)
                #pragma unroll
                for (int j = 0; j < 8; j++)
                    acc[i][j] = fmaf(ar[i], br[j], acc[i][j]);
        }
        __syncthreads();
    }

    #pragma unroll
    for (int i = 0; i < 8; i++) {
        const int r = by * 128 + ty * 8 + i;
        #pragma unroll
        for (int j = 0; j < 8; j += 4) {
            const int c = bx * 128 + tx * 8 + j;
            float4 o;
            o.x = acc[i][j + 0] + bias[c + 0];
            o.y = acc[i][j + 1] + bias[c + 1];
            o.z = acc[i][j + 2] + bias[c + 2];
            o.w = acc[i][j + 3] + bias[c + 3];
            *(float4*)(C + (size_t)r * N + c) = o;
        }
    }
}

// ---------------------------------------------------------------------------
// Causal flash attention.  grid = (16 q-tiles, 32 heads), block = 128.
// One thread per q-row.  K/V tiles of 32 rows in smem (broadcast reads).
// Online softmax with running max/sum.  Q pre-scaled by 1/sqrt(64).
// ---------------------------------------------------------------------------
__global__ __launch_bounds__(128)
void flash_attn(const float* __restrict__ qbuf, const float* __restrict__ kbuf,
                const float* __restrict__ vbuf, float* __restrict__ obuf)
{
    const int qt  = blockIdx.x;          // 0..15 (128 rows each)
    const int h   = blockIdx.y;          // 0..31
    const int g   = h >> 2;              // repeat_interleave: group = h / 4
    const int tid = threadIdx.x;         // 0..127
    const int row = qt * 128 + tid;

    __shared__ float Ks[32][64];
    __shared__ float Vs[32][64];

    float q[64], acc[64];
    const float scale = 0.125f;          // 1/sqrt(DK)

    const float* qrow = qbuf + (size_t)row * D_MODEL + h * DK;
    #pragma unroll
    for (int d = 0; d < 64; d += 4) {
        float4 t = *(const float4*)(qrow + d);
        q[d] = t.x * scale; q[d + 1] = t.y * scale;
        q[d + 2] = t.z * scale; q[d + 3] = t.w * scale;
    }
    #pragma unroll
    for (int d = 0; d < 64; d++) acc[d] = 0.f;

    float m = -1e30f, l = 0.f;

    const int ktiles = (qt + 1) * 4;     // tiles of 32 k-rows, causal bound

    for (int kt = 0; kt < ktiles; kt++) {
        __syncthreads();
        // cooperative load: 2048 floats per buffer = 512 float4 / 128 thr = 4 ea
        const int base = kt * 32;
        #pragma unroll
        for (int i = 0; i < 4; i++) {
            const int f  = tid + i * 128;
            const int r  = f >> 4;
            const int c4 = (f & 15) * 4;
            const size_t off = (size_t)(base + r) * KV_W + g * DK + c4;
            *(float4*)(&Ks[r][c4]) = *(const float4*)(kbuf + off);
            *(float4*)(&Vs[r][c4]) = *(const float4*)(vbuf + off);
        }
        __syncthreads();

        float s[32];
        float tmax = -1e30f;
        #pragma unroll
        for (int j = 0; j < 32; j++) {
            float dot = 0.f;
            #pragma unroll
            for (int d = 0; d < 64; d += 4) {
                float4 kk = *(const float4*)(&Ks[j][d]);
                dot = fmaf(q[d], kk.x, dot);
                dot = fmaf(q[d + 1], kk.y, dot);
                dot = fmaf(q[d + 2], kk.z, dot);
                dot = fmaf(q[d + 3], kk.w, dot);
            }
            const int col = base + j;
            s[j] = (col <= row) ? dot : -1e30f;
            tmax = fmaxf(tmax, s[j]);
        }

        const float mnew = fmaxf(m, tmax);
        const float corr = __expf(m - mnew);
        float psum = 0.f;
        #pragma unroll
        for (int j = 0; j < 32; j++) {
            s[j] = __expf(s[j] - mnew);
            psum += s[j];
        }
        l = l * corr + psum;
        #pragma unroll
        for (int d = 0; d < 64; d++) acc[d] *= corr;

        #pragma unroll
        for (int j = 0; j < 32; j++) {
            const float p = s[j];
            #pragma unroll
            for (int d = 0; d < 64; d += 4) {
                float4 vv = *(const float4*)(&Vs[j][d]);
                acc[d]     = fmaf(p, vv.x, acc[d]);
                acc[d + 1] = fmaf(p, vv.y, acc[d + 1]);
                acc[d + 2] = fmaf(p, vv.z, acc[d + 2]);
                acc[d + 3] = fmaf(p, vv.w, acc[d + 3]);
            }
        }
        m = mnew;
    }

    const float inv = 1.f / l;
    float* orow = obuf + (size_t)row * D_MODEL + h * DV;
    #pragma unroll
    for (int d = 0; d < 64; d += 4) {
        float4 o;
        o.x = acc[d] * inv; o.y = acc[d + 1] * inv;
        o.z = acc[d + 2] * inv; o.w = acc[d + 3] * inv;
        *(float4*)(orow + d) = o;
    }
}

// ---------------------------------------------------------------------------
// Launch
// ---------------------------------------------------------------------------
extern "C" void kernel_launch(void* const* d_in, const int* in_sizes, int n_in,
                              void* d_out, int out_size)
{
    const float* queries = (const float*)d_in[0];
    const float* keys    = (const float*)d_in[1];
    const float* values  = (const float*)d_in[2];
    const float* Wq      = (const float*)d_in[3];
    const float* bq      = (const float*)d_in[4];
    const float* Wk      = (const float*)d_in[5];
    const float* bk      = (const float*)d_in[6];
    const float* Wv      = (const float*)d_in[7];
    const float* bv      = (const float*)d_in[8];
    const float* Wo      = (const float*)d_in[9];
    const float* bo      = (const float*)d_in[10];
    float*       out     = (float*)d_out;

    float *pq, *pk, *pv, *pa;
    cudaGetSymbolAddress((void**)&pq, g_q);
    cudaGetSymbolAddress((void**)&pk, g_k);
    cudaGetSymbolAddress((void**)&pv, g_v);
    cudaGetSymbolAddress((void**)&pa, g_attn);

    // Q projection: [2048,2048] @ [2048,2048]
    sgemm_bias<<<dim3(D_MODEL / 128, S_LEN / 128), 256>>>(
        queries, Wq, bq, pq, S_LEN, D_MODEL, D_MODEL);
    // K projection: [2048,2048] @ [2048,512]
    sgemm_bias<<<dim3(KV_W / 128, S_LEN / 128), 256>>>(
        keys, Wk, bk, pk, S_LEN, KV_W, D_MODEL);
    // V projection
    sgemm_bias<<<dim3(KV_W / 128, S_LEN / 128), 256>>>(
        values, Wv, bv, pv, S_LEN, KV_W, D_MODEL);

    // Causal GQA flash attention
    flash_attn<<<dim3(S_LEN / 128, H_Q), 128>>>(pq, pk, pv, pa);

    // Output projection: [2048,2048] @ [2048,2048]
    sgemm_bias<<<dim3(D_MODEL / 128, S_LEN / 128), 256>>>(
        pa, Wo, bo, out, S_LEN, D_MODEL, D_MODEL);
}

// round 3
// speedup vs baseline: 2.9659x; 2.9659x over previous
#include <cuda_runtime.h>
#include <cuda_bf16.h>
#include <cuda_fp16.h>
#include <cstdint>

// ===========================================================================
// GQA layer, sm_103 baseline-PTX path: mma.sync (HMMA) everywhere.
//   - projections: bf16 split-2 GEMM (3-pass) via mma.sync.m16n8k16
//   - attention:   fp16 FA-2 via mma.sync.m16n8k16, fp32 softmax
// ===========================================================================

#define S_LEN   2048
#define D_MODEL 2048
#define H_Q     32
#define KV_W    512
#define GK      2048
#define QSCALE  0.1803368801111244f   // 0.125 * log2(e)

// ------------------------------ scratch ------------------------------------
__device__ __align__(16) __half g_qh[S_LEN * D_MODEL];     // fp16 Q (pre-scaled)
__device__ __align__(16) __half g_kh[S_LEN * KV_W];        // fp16 K
__device__ __align__(16) __half g_vh[S_LEN * KV_W];        // fp16 V
__device__ __align__(16) float  g_attn[S_LEN * D_MODEL];   // fp32 attn out

// split activations (reused for queries/keys/values/attn inputs)
__device__ __align__(16) __nv_bfloat16 g_ahi[S_LEN * D_MODEL];
__device__ __align__(16) __nv_bfloat16 g_alo[S_LEN * D_MODEL];

// transposed + split weights, [N][K]
__device__ __align__(16) __nv_bfloat16 g_wq_hi[D_MODEL * GK];
__device__ __align__(16) __nv_bfloat16 g_wq_lo[D_MODEL * GK];
__device__ __align__(16) __nv_bfloat16 g_wk_hi[KV_W * GK];
__device__ __align__(16) __nv_bfloat16 g_wk_lo[KV_W * GK];
__device__ __align__(16) __nv_bfloat16 g_wv_hi[KV_W * GK];
__device__ __align__(16) __nv_bfloat16 g_wv_lo[KV_W * GK];
__device__ __align__(16) __nv_bfloat16 g_wo_hi[D_MODEL * GK];
__device__ __align__(16) __nv_bfloat16 g_wo_lo[D_MODEL * GK];

// ------------------------------ helpers ------------------------------------
__device__ __forceinline__ uint32_t smem_u32(const void* p) {
    uint32_t a;
    asm("{ .reg .u64 t; cvta.to.shared.u64 t, %1; cvt.u32.u64 %0, t; }"
        : "=r"(a) : "l"(p));
    return a;
}

#define CP16(dst, src) \
    asm volatile("cp.async.cg.shared.global [%0], [%1], 16;" \
                 :: "r"(dst), "l"(src))
#define CPCOMMIT() asm volatile("cp.async.commit_group;" ::: "memory")
#define CPWAIT(n)  asm volatile("cp.async.wait_group %0;" :: "n"(n) : "memory")

__device__ __forceinline__ void ldsm_x4(uint32_t& r0, uint32_t& r1,
                                        uint32_t& r2, uint32_t& r3, uint32_t a) {
    asm volatile("ldmatrix.sync.aligned.m8n8.x4.shared.b16 {%0,%1,%2,%3}, [%4];"
                 : "=r"(r0), "=r"(r1), "=r"(r2), "=r"(r3) : "r"(a));
}
__device__ __forceinline__ void ldsm_x4t(uint32_t& r0, uint32_t& r1,
                                         uint32_t& r2, uint32_t& r3, uint32_t a) {
    asm volatile("ldmatrix.sync.aligned.m8n8.x4.trans.shared.b16 {%0,%1,%2,%3}, [%4];"
                 : "=r"(r0), "=r"(r1), "=r"(r2), "=r"(r3) : "r"(a));
}

__device__ __forceinline__ void mma_bf16(float* c, const uint32_t* a,
                                         uint32_t b0, uint32_t b1) {
    asm volatile("mma.sync.aligned.m16n8k16.row.col.f32.bf16.bf16.f32 "
                 "{%0,%1,%2,%3}, {%4,%5,%6,%7}, {%8,%9}, {%0,%1,%2,%3};"
                 : "+f"(c[0]), "+f"(c[1]), "+f"(c[2]), "+f"(c[3])
                 : "r"(a[0]), "r"(a[1]), "r"(a[2]), "r"(a[3]), "r"(b0), "r"(b1));
}
__device__ __forceinline__ void mma_f16(float* c, const uint32_t* a,
                                        uint32_t b0, uint32_t b1) {
    asm volatile("mma.sync.aligned.m16n8k16.row.col.f32.f16.f16.f32 "
                 "{%0,%1,%2,%3}, {%4,%5,%6,%7}, {%8,%9}, {%0,%1,%2,%3};"
                 : "+f"(c[0]), "+f"(c[1]), "+f"(c[2]), "+f"(c[3])
                 : "r"(a[0]), "r"(a[1]), "r"(a[2]), "r"(a[3]), "r"(b0), "r"(b1));
}

// ---------------------------------------------------------------------------
// asplit: fp32 activations -> bf16 hi/lo (elementwise, float4)
// ---------------------------------------------------------------------------
__global__ __launch_bounds__(256)
void asplit(const float4* __restrict__ A, __nv_bfloat16* __restrict__ hi,
            __nv_bfloat16* __restrict__ lo)
{
    const int i = blockIdx.x * 256 + threadIdx.x;
    float4 v = A[i];
    __nv_bfloat162 h0 = __floats2bfloat162_rn(v.x, v.y);
    __nv_bfloat162 h1 = __floats2bfloat162_rn(v.z, v.w);
    __nv_bfloat162 l0 = __floats2bfloat162_rn(v.x - __bfloat162float(h0.x),
                                              v.y - __bfloat162float(h0.y));
    __nv_bfloat162 l1 = __floats2bfloat162_rn(v.z - __bfloat162float(h1.x),
                                              v.w - __bfloat162float(h1.y));
    uint2 uh = make_uint2(*(uint32_t*)&h0, *(uint32_t*)&h1);
    uint2 ul = make_uint2(*(uint32_t*)&l0, *(uint32_t*)&l1);
    *(uint2*)(hi + (size_t)i * 4) = uh;
    *(uint2*)(lo + (size_t)i * 4) = ul;
}

// ---------------------------------------------------------------------------
// wsplit: W[K,N] fp32 -> hi/lo bf16 [N][K]  (32x32 smem transpose)
// ---------------------------------------------------------------------------
__global__ __launch_bounds__(256)
void wsplit(const float* __restrict__ W, __nv_bfloat16* __restrict__ hi,
            __nv_bfloat16* __restrict__ lo, int Ncols)
{
    __shared__ float tile[32][33];
    const int bx = blockIdx.x, by = blockIdx.y;
    const int tx = threadIdx.x & 31, ty = threadIdx.x >> 5;

    #pragma unroll
    for (int i = 0; i < 32; i += 8)
        tile[ty + i][tx] = W[(size_t)(by * 32 + ty + i) * Ncols + bx * 32 + tx];
    __syncthreads();
    #pragma unroll
    for (int i = 0; i < 32; i += 8) {
        const int n = bx * 32 + ty + i;
        const int k = by * 32 + tx;
        float x = tile[tx][ty + i];
        __nv_bfloat16 h = __float2bfloat16_rn(x);
        hi[(size_t)n * GK + k] = h;
        lo[(size_t)n * GK + k] = __float2bfloat16_rn(x - __bfloat162float(h));
    }
}

// ---------------------------------------------------------------------------
// GEMM via mma.sync, bf16 split-2.  C = A @ B^T + bias,  A [M][K] hi/lo,
// B [N][K] hi/lo.  128x128 tile, BK=32, 256 thr (8 warps, warp tile 32x64).
// MODE 0: float out; MODE 1: half out; MODE 2: half out * QSCALE.
// ---------------------------------------------------------------------------
#define GSTAGE 32768   // 4 x 8KB per stage

template <int MODE>
__global__ __launch_bounds__(256)
void gemm_mma(const __nv_bfloat16* __restrict__ Ahi, const __nv_bfloat16* __restrict__ Alo,
              const __nv_bfloat16* __restrict__ Bhi, const __nv_bfloat16* __restrict__ Blo,
              const float* __restrict__ bias, void* __restrict__ Cout, int Ntot)
{
    extern __shared__ char sm[];
    const uint32_t sb = smem_u32(sm);
    const int tid  = threadIdx.x;
    const int lane = tid & 31;
    const int wid  = tid >> 5;
    const int wm   = (wid & 3) * 32;
    const int wn   = (wid >> 2) * 64;
    const int m0   = blockIdx.y * 128, n0 = blockIdx.x * 128;
    const int gg   = lane >> 2, tg = lane & 3;
    const int mi   = lane >> 3;

    float acc[2][8][4];
    #pragma unroll
    for (int a = 0; a < 2; a++)
        #pragma unroll
        for (int b = 0; b < 8; b++)
            #pragma unroll
            for (int c = 0; c < 4; c++) acc[a][b][c] = 0.f;

    auto load_stage = [&](int it) {
        const uint32_t st = sb + (it & 1) * GSTAGE;
        const int k0 = it * 32;
        #pragma unroll
        for (int t = 0; t < 8; t++) {
            const int f   = tid + (t & 1) * 256;   // 0..511
            const int row = f >> 2, c = f & 3;
            const int sel = t >> 1;                // 0 Ah, 1 Al, 2 Bh, 3 Bl
            const uint32_t dst = st + sel * 8192 + row * 64 +
                                 ((c ^ ((row >> 1) & 3)) * 16);
            const __nv_bfloat16* src;
            if      (sel == 0) src = Ahi + (size_t)(m0 + row) * GK + k0 + c * 8;
            else if (sel == 1) src = Alo + (size_t)(m0 + row) * GK + k0 + c * 8;
            else if (sel == 2) src = Bhi + (size_t)(n0 + row) * GK + k0 + c * 8;
            else               src = Blo + (size_t)(n0 + row) * GK + k0 + c * 8;
            CP16(dst, src);
        }
    };

    load_stage(0);
    CPCOMMIT();

    const int NIT = GK / 32;
    for (int it = 0; it < NIT; it++) {
        if (it + 1 < NIT) { load_stage(it + 1); CPCOMMIT(); CPWAIT(1); }
        else              { CPWAIT(0); }
        __syncthreads();
        const uint32_t st = sb + (it & 1) * GSTAGE;

        #pragma unroll
        for (int s = 0; s < 2; s++) {
            uint32_t aH[2][4], aL[2][4];
            #pragma unroll
            for (int mt = 0; mt < 2; mt++) {
                const int r = wm + mt * 16 + (mi & 1) * 8 + (lane & 7);
                const int c = 2 * s + (mi >> 1);
                const uint32_t ad = st + r * 64 + ((c ^ ((r >> 1) & 3)) * 16);
                ldsm_x4(aH[mt][0], aH[mt][1], aH[mt][2], aH[mt][3], ad);
                ldsm_x4(aL[mt][0], aL[mt][1], aL[mt][2], aL[mt][3], ad + 8192);
            }
            uint32_t bH[8][2], bL[8][2];
            #pragma unroll
            for (int nt = 0; nt < 4; nt++) {
                const int r = wn + nt * 16 + (mi >> 1) * 8 + (lane & 7);
                const int c = 2 * s + (mi & 1);
                const uint32_t bd = st + 16384 + r * 64 + ((c ^ ((r >> 1) & 3)) * 16);
                ldsm_x4(bH[2*nt][0], bH[2*nt][1], bH[2*nt+1][0], bH[2*nt+1][1], bd);
                ldsm_x4(bL[2*nt][0], bL[2*nt][1], bL[2*nt+1][0], bL[2*nt+1][1], bd + 8192);
            }
            #pragma unroll
            for (int mt = 0; mt < 2; mt++)
                #pragma unroll
                for (int n = 0; n < 8; n++) {
                    mma_bf16(acc[mt][n], aH[mt], bH[n][0], bH[n][1]);
                    mma_bf16(acc[mt][n], aH[mt], bL[n][0], bL[n][1]);
                    mma_bf16(acc[mt][n], aL[mt], bH[n][0], bH[n][1]);
                }
        }
        __syncthreads();
    }

    // epilogue
    #pragma unroll
    for (int mt = 0; mt < 2; mt++)
        #pragma unroll
        for (int n = 0; n < 8; n++) {
            const int r0  = m0 + wm + mt * 16 + gg;
            const int col = n0 + wn + n * 8 + tg * 2;
            const float b0 = bias[col], b1 = bias[col + 1];
            if (MODE == 0) {
                float* C = (float*)Cout;
                *(float2*)(C + (size_t)r0 * Ntot + col) =
                    make_float2(acc[mt][n][0] + b0, acc[mt][n][1] + b1);
                *(float2*)(C + (size_t)(r0 + 8) * Ntot + col) =
                    make_float2(acc[mt][n][2] + b0, acc[mt][n][3] + b1);
            } else {
                const float sc = (MODE == 2) ? QSCALE : 1.0f;
                __half* C = (__half*)Cout;
                __half2 h0 = __floats2half2_rn((acc[mt][n][0] + b0) * sc,
                                               (acc[mt][n][1] + b1) * sc);
                __half2 h1 = __floats2half2_rn((acc[mt][n][2] + b0) * sc,
                                               (acc[mt][n][3] + b1) * sc);
                *(__half2*)(C + (size_t)r0 * Ntot + col) = h0;
                *(__half2*)(C + (size_t)(r0 + 8) * Ntot + col) = h1;
            }
        }
}

// ---------------------------------------------------------------------------
// fp16 HMMA causal flash attention.  64 q-rows x 64 kv per tile, 4 warps.
// Q pre-scaled by 0.125*log2(e);  softmax in exp2 domain.
// ---------------------------------------------------------------------------
__global__ __launch_bounds__(128)
void flash(const __half* __restrict__ qbuf, const __half* __restrict__ kbuf,
           const __half* __restrict__ vbuf, float* __restrict__ obuf)
{
    __shared__ __align__(16) __half sQ[64 * 64];
    __shared__ __align__(16) __half sK[2][64 * 64];
    __shared__ __align__(16) __half sV[2][64 * 64];

    const int qt   = (int)gridDim.x - 1 - (int)blockIdx.x;
    const int h    = blockIdx.y;
    const int g    = h >> 2;
    const int tid  = threadIdx.x;
    const int warp = tid >> 5, lane = tid & 31;
    const int gg   = lane >> 2, tg = lane & 3;
    const int mi   = lane >> 3;
    const int q0   = qt * 64;

    const uint32_t qb  = smem_u32(sQ);
    const uint32_t kb0 = smem_u32(sK);
    const uint32_t vb0 = smem_u32(sV);

    // load Q
    #pragma unroll
    for (int i = 0; i < 4; i++) {
        const int f = tid + i * 128;
        const int r = f >> 3, c = f & 7;
        CP16(qb + r * 128 + ((c ^ (r & 7)) * 16),
             qbuf + (size_t)(q0 + r) * D_MODEL + h * 64 + c * 8);
    }
    auto loadKV = [&](int kt) {
        const uint32_t ko = kb0 + (kt & 1) * 8192;
        const uint32_t vo = vb0 + (kt & 1) * 8192;
        #pragma unroll
        for (int i = 0; i < 4; i++) {
            const int f = tid + i * 128;
            const int r = f >> 3, c = f & 7;
            const size_t src = (size_t)(kt * 64 + r) * KV_W + g * 64 + c * 8;
            const uint32_t d = r * 128 + ((c ^ (r & 7)) * 16);
            CP16(ko + d, kbuf + src);
            CP16(vo + d, vbuf + src);
        }
    };
    loadKV(0);
    CPCOMMIT();
    CPWAIT(0);
    __syncthreads();

    // Q fragments (warp-resident)
    uint32_t qa[4][4];
    {
        const int r = warp * 16 + (mi & 1) * 8 + (lane & 7);
        #pragma unroll
        for (int s = 0; s < 4; s++) {
            const int c = 2 * s + (mi >> 1);
            ldsm_x4(qa[s][0], qa[s][1], qa[s][2], qa[s][3],
                    qb + r * 128 + ((c ^ (r & 7)) * 16));
        }
    }

    float o[8][4];
    #pragma unroll
    for (int n = 0; n < 8; n++)
        #pragma unroll
        for (int c = 0; c < 4; c++) o[n][c] = 0.f;
    float m0v = -1e30f, m1v = -1e30f, l0 = 0.f, l1 = 0.f;
    const int r0g = q0 + warp * 16 + gg;
    const int r1g = r0g + 8;

    for (int kt = 0; kt <= qt; kt++) {
        if (kt < qt) { loadKV(kt + 1); CPCOMMIT(); CPWAIT(1); }
        else         { CPWAIT(0); }
        __syncthreads();
        const uint32_t ko = kb0 + (kt & 1) * 8192;
        const uint32_t vo = vb0 + (kt & 1) * 8192;

        // ---- S = Q K^T ----
        float sc[8][4];
        #pragma unroll
        for (int n = 0; n < 8; n++)
            #pragma unroll
            for (int c = 0; c < 4; c++) sc[n][c] = 0.f;

        #pragma unroll
        for (int s = 0; s < 4; s++)
            #pragma unroll
            for (int nt = 0; nt < 4; nt++) {
                const int r = nt * 16 + (mi >> 1) * 8 + (lane & 7);
                const int c = 2 * s + (mi & 1);
                uint32_t b0r, b1r, b2r, b3r;
                ldsm_x4(b0r, b1r, b2r, b3r, ko + r * 128 + ((c ^ (r & 7)) * 16));
                mma_f16(sc[2 * nt],     qa[s], b0r, b1r);
                mma_f16(sc[2 * nt + 1], qa[s], b2r, b3r);
            }

        // causal mask on diagonal tile
        if (kt == qt) {
            #pragma unroll
            for (int n = 0; n < 8; n++) {
                const int col = kt * 64 + n * 8 + tg * 2;
                if (col     > r0g) sc[n][0] = -1e30f;
                if (col + 1 > r0g) sc[n][1] = -1e30f;
                if (col     > r1g) sc[n][2] = -1e30f;
                if (col + 1 > r1g) sc[n][3] = -1e30f;
            }
        }

        // ---- online softmax (exp2 domain) ----
        float mx0 = -1e30f, mx1 = -1e30f;
        #pragma unroll
        for (int n = 0; n < 8; n++) {
            mx0 = fmaxf(mx0, fmaxf(sc[n][0], sc[n][1]));
            mx1 = fmaxf(mx1, fmaxf(sc[n][2], sc[n][3]));
        }
        mx0 = fmaxf(mx0, __shfl_xor_sync(0xffffffffu, mx0, 1));
        mx0 = fmaxf(mx0, __shfl_xor_sync(0xffffffffu, mx0, 2));
        mx1 = fmaxf(mx1, __shfl_xor_sync(0xffffffffu, mx1, 1));
        mx1 = fmaxf(mx1, __shfl_xor_sync(0xffffffffu, mx1, 2));
        const float mn0 = fmaxf(m0v, mx0), mn1 = fmaxf(m1v, mx1);
        const float c0 = exp2f(m0v - mn0), c1 = exp2f(m1v - mn1);
        m0v = mn0; m1v = mn1;

        float ps0 = 0.f, ps1 = 0.f;
        #pragma unroll
        for (int n = 0; n < 8; n++) {
            sc[n][0] = exp2f(sc[n][0] - mn0);
            sc[n][1] = exp2f(sc[n][1] - mn0);
            sc[n][2] = exp2f(sc[n][2] - mn1);
            sc[n][3] = exp2f(sc[n][3] - mn1);
            ps0 += sc[n][0] + sc[n][1];
            ps1 += sc[n][2] + sc[n][3];
        }
        l0 = l0 * c0 + ps0;
        l1 = l1 * c1 + ps1;
        #pragma unroll
        for (int n = 0; n < 8; n++) {
            o[n][0] *= c0; o[n][1] *= c0;
            o[n][2] *= c1; o[n][3] *= c1;
        }

        // P fragments (fp16)
        uint32_t pa[4][4];
        #pragma unroll
        for (int s = 0; s < 4; s++) {
            __half2 p0 = __floats2half2_rn(sc[2*s][0],   sc[2*s][1]);
            __half2 p1 = __floats2half2_rn(sc[2*s][2],   sc[2*s][3]);
            __half2 p2 = __floats2half2_rn(sc[2*s+1][0], sc[2*s+1][1]);
            __half2 p3 = __floats2half2_rn(sc[2*s+1][2], sc[2*s+1][3]);
            pa[s][0] = *(uint32_t*)&p0;
            pa[s][1] = *(uint32_t*)&p1;
            pa[s][2] = *(uint32_t*)&p2;
            pa[s][3] = *(uint32_t*)&p3;
        }

        // ---- O += P V ----
        #pragma unroll
        for (int s = 0; s < 4; s++)
            #pragma unroll
            for (int nt = 0; nt < 4; nt++) {
                const int r = s * 16 + (mi & 1) * 8 + (lane & 7);
                const int c = 2 * nt + (mi >> 1);
                uint32_t b0r, b1r, b2r, b3r;
                ldsm_x4t(b0r, b1r, b2r, b3r, vo + r * 128 + ((c ^ (r & 7)) * 16));
                mma_f16(o[2 * nt],     pa[s], b0r, b1r);
                mma_f16(o[2 * nt + 1], pa[s], b2r, b3r);
            }
        __syncthreads();
    }

    // reduce l across the 4 lanes of each row, normalize, store
    l0 += __shfl_xor_sync(0xffffffffu, l0, 1);
    l0 += __shfl_xor_sync(0xffffffffu, l0, 2);
    l1 += __shfl_xor_sync(0xffffffffu, l1, 1);
    l1 += __shfl_xor_sync(0xffffffffu, l1, 2);
    const float i0 = 1.f / l0, i1 = 1.f / l1;

    #pragma unroll
    for (int n = 0; n < 8; n++) {
        const int col = h * 64 + n * 8 + tg * 2;
        *(float2*)(obuf + (size_t)r0g * D_MODEL + col) =
            make_float2(o[n][0] * i0, o[n][1] * i0);
        *(float2*)(obuf + (size_t)r1g * D_MODEL + col) =
            make_float2(o[n][2] * i1, o[n][3] * i1);
    }
}

// ---------------------------------------------------------------------------
// Launch
// ---------------------------------------------------------------------------
extern "C" void kernel_launch(void* const* d_in, const int* in_sizes, int n_in,
                              void* d_out, int out_size)
{
    const float* queries = (const float*)d_in[0];
    const float* keys    = (const float*)d_in[1];
    const float* values  = (const float*)d_in[2];
    const float* Wq      = (const float*)d_in[3];
    const float* bq      = (const float*)d_in[4];
    const float* Wk      = (const float*)d_in[5];
    const float* bk      = (const float*)d_in[6];
    const float* Wv      = (const float*)d_in[7];
    const float* bv      = (const float*)d_in[8];
    const float* Wo      = (const float*)d_in[9];
    const float* bo      = (const float*)d_in[10];
    float*       out     = (float*)d_out;

    __half *qh, *kh, *vh;  float *attn;
    __nv_bfloat16 *ahi, *alo;
    __nv_bfloat16 *wqh, *wql, *wkh, *wkl, *wvh, *wvl, *woh, *wol;
    cudaGetSymbolAddress((void**)&qh,  g_qh);
    cudaGetSymbolAddress((void**)&kh,  g_kh);
    cudaGetSymbolAddress((void**)&vh,  g_vh);
    cudaGetSymbolAddress((void**)&attn, g_attn);
    cudaGetSymbolAddress((void**)&ahi, g_ahi);
    cudaGetSymbolAddress((void**)&alo, g_alo);
    cudaGetSymbolAddress((void**)&wqh, g_wq_hi);
    cudaGetSymbolAddress((void**)&wql, g_wq_lo);
    cudaGetSymbolAddress((void**)&wkh, g_wk_hi);
    cudaGetSymbolAddress((void**)&wkl, g_wk_lo);
    cudaGetSymbolAddress((void**)&wvh, g_wv_hi);
    cudaGetSymbolAddress((void**)&wvl, g_wv_lo);
    cudaGetSymbolAddress((void**)&woh, g_wo_hi);
    cudaGetSymbolAddress((void**)&wol, g_wo_lo);

    cudaFuncSetAttribute(gemm_mma<0>, cudaFuncAttributeMaxDynamicSharedMemorySize, 2 * GSTAGE);
    cudaFuncSetAttribute(gemm_mma<1>, cudaFuncAttributeMaxDynamicSharedMemorySize, 2 * GSTAGE);
    cudaFuncSetAttribute(gemm_mma<2>, cudaFuncAttributeMaxDynamicSharedMemorySize, 2 * GSTAGE);

    const int NELEM4 = S_LEN * D_MODEL / 4;

    // weight prep
    wsplit<<<dim3(D_MODEL / 32, GK / 32), 256>>>(Wq, wqh, wql, D_MODEL);
    wsplit<<<dim3(KV_W / 32,  GK / 32), 256>>>(Wk, wkh, wkl, KV_W);
    wsplit<<<dim3(KV_W / 32,  GK / 32), 256>>>(Wv, wvh, wvl, KV_W);
    wsplit<<<dim3(D_MODEL / 32, GK / 32), 256>>>(Wo, woh, wol, D_MODEL);

    // Q projection  (half out, pre-scaled)
    asplit<<<NELEM4 / 256, 256>>>((const float4*)queries, ahi, alo);
    gemm_mma<2><<<dim3(D_MODEL / 128, S_LEN / 128), 256, 2 * GSTAGE>>>(
        ahi, alo, wqh, wql, bq, qh, D_MODEL);

    // K projection (half out)
    asplit<<<NELEM4 / 256, 256>>>((const float4*)keys, ahi, alo);
    gemm_mma<1><<<dim3(KV_W / 128, S_LEN / 128), 256, 2 * GSTAGE>>>(
        ahi, alo, wkh, wkl, bk, kh, KV_W);

    // V projection (half out)
    asplit<<<NELEM4 / 256, 256>>>((const float4*)values, ahi, alo);
    gemm_mma<1><<<dim3(KV_W / 128, S_LEN / 128), 256, 2 * GSTAGE>>>(
        ahi, alo, wvh, wvl, bv, vh, KV_W);

    // causal GQA flash attention (fp16 HMMA)
    flash<<<dim3(S_LEN / 64, H_Q), 128>>>(qh, kh, vh, attn);

    // output projection (float out)
    asplit<<<NELEM4 / 256, 256>>>((const float4*)attn, ahi, alo);
    gemm_mma<0><<<dim3(D_MODEL / 128, S_LEN / 128), 256, 2 * GSTAGE>>>(
        ahi, alo, woh, wol, bo, out, D_MODEL);
}

// round 4
// speedup vs baseline: 4.6970x; 1.5837x over previous
#include <cuda_runtime.h>
#include <cuda_bf16.h>
#include <cuda_fp16.h>
#include <cstdint>

// ===========================================================================
// GQA layer, sm_103 baseline-PTX path: mma.sync (HMMA) everywhere.
//   - projections: bf16 split-2 GEMM (3-pass) via mma.sync.m16n8k16
//       CTA tile 256x128, warp tile 64x64, BK=32, 2-stage cp.async
//   - attention:   fp16 FA-2 via mma.sync.m16n8k16, fp32 softmax
// ===========================================================================

#define S_LEN   2048
#define D_MODEL 2048
#define H_Q     32
#define KV_W    512
#define GK      2048
#define QSCALE  0.1803368801111244f   // 0.125 * log2(e)

// ------------------------------ scratch ------------------------------------
__device__ __align__(16) __half g_qh[S_LEN * D_MODEL];
__device__ __align__(16) __half g_kh[S_LEN * KV_W];
__device__ __align__(16) __half g_vh[S_LEN * KV_W];
__device__ __align__(16) float  g_attn[S_LEN * D_MODEL];

// split activations: buffer A (queries / attn), buffer B (keys), buffer C (values)
__device__ __align__(16) __nv_bfloat16 g_ahi[S_LEN * D_MODEL];
__device__ __align__(16) __nv_bfloat16 g_alo[S_LEN * D_MODEL];
__device__ __align__(16) __nv_bfloat16 g_bhi[S_LEN * D_MODEL];
__device__ __align__(16) __nv_bfloat16 g_blo[S_LEN * D_MODEL];
__device__ __align__(16) __nv_bfloat16 g_chi[S_LEN * D_MODEL];
__device__ __align__(16) __nv_bfloat16 g_clo[S_LEN * D_MODEL];

// transposed + split weights, [N][K]
__device__ __align__(16) __nv_bfloat16 g_wq_hi[D_MODEL * GK];
__device__ __align__(16) __nv_bfloat16 g_wq_lo[D_MODEL * GK];
__device__ __align__(16) __nv_bfloat16 g_wk_hi[KV_W * GK];
__device__ __align__(16) __nv_bfloat16 g_wk_lo[KV_W * GK];
__device__ __align__(16) __nv_bfloat16 g_wv_hi[KV_W * GK];
__device__ __align__(16) __nv_bfloat16 g_wv_lo[KV_W * GK];
__device__ __align__(16) __nv_bfloat16 g_wo_hi[D_MODEL * GK];
__device__ __align__(16) __nv_bfloat16 g_wo_lo[D_MODEL * GK];

// ------------------------------ helpers ------------------------------------
__device__ __forceinline__ uint32_t smem_u32(const void* p) {
    uint32_t a;
    asm("{ .reg .u64 t; cvta.to.shared.u64 t, %1; cvt.u32.u64 %0, t; }"
        : "=r"(a) : "l"(p));
    return a;
}

#define CP16(dst, src) \
    asm volatile("cp.async.cg.shared.global [%0], [%1], 16;" \
                 :: "r"(dst), "l"(src))
#define CPCOMMIT() asm volatile("cp.async.commit_group;" ::: "memory")
#define CPWAIT(n)  asm volatile("cp.async.wait_group %0;" :: "n"(n) : "memory")

__device__ __forceinline__ void ldsm_x4(uint32_t& r0, uint32_t& r1,
                                        uint32_t& r2, uint32_t& r3, uint32_t a) {
    asm volatile("ldmatrix.sync.aligned.m8n8.x4.shared.b16 {%0,%1,%2,%3}, [%4];"
                 : "=r"(r0), "=r"(r1), "=r"(r2), "=r"(r3) : "r"(a));
}
__device__ __forceinline__ void ldsm_x4t(uint32_t& r0, uint32_t& r1,
                                         uint32_t& r2, uint32_t& r3, uint32_t a) {
    asm volatile("ldmatrix.sync.aligned.m8n8.x4.trans.shared.b16 {%0,%1,%2,%3}, [%4];"
                 : "=r"(r0), "=r"(r1), "=r"(r2), "=r"(r3) : "r"(a));
}

__device__ __forceinline__ void mma_bf16(float* c, const uint32_t* a,
                                         uint32_t b0, uint32_t b1) {
    asm volatile("mma.sync.aligned.m16n8k16.row.col.f32.bf16.bf16.f32 "
                 "{%0,%1,%2,%3}, {%4,%5,%6,%7}, {%8,%9}, {%0,%1,%2,%3};"
                 : "+f"(c[0]), "+f"(c[1]), "+f"(c[2]), "+f"(c[3])
                 : "r"(a[0]), "r"(a[1]), "r"(a[2]), "r"(a[3]), "r"(b0), "r"(b1));
}
__device__ __forceinline__ void mma_f16(float* c, const uint32_t* a,
                                        uint32_t b0, uint32_t b1) {
    asm volatile("mma.sync.aligned.m16n8k16.row.col.f32.f16.f16.f32 "
                 "{%0,%1,%2,%3}, {%4,%5,%6,%7}, {%8,%9}, {%0,%1,%2,%3};"
                 : "+f"(c[0]), "+f"(c[1]), "+f"(c[2]), "+f"(c[3])
                 : "r"(a[0]), "r"(a[1]), "r"(a[2]), "r"(a[3]), "r"(b0), "r"(b1));
}

// ---------------------------------------------------------------------------
// asplit: fp32 activations -> bf16 hi/lo (elementwise, float4)
// ---------------------------------------------------------------------------
__global__ __launch_bounds__(256)
void asplit(const float4* __restrict__ A, __nv_bfloat16* __restrict__ hi,
            __nv_bfloat16* __restrict__ lo)
{
    const int i = blockIdx.x * 256 + threadIdx.x;
    float4 v = A[i];
    __nv_bfloat162 h0 = __floats2bfloat162_rn(v.x, v.y);
    __nv_bfloat162 h1 = __floats2bfloat162_rn(v.z, v.w);
    __nv_bfloat162 l0 = __floats2bfloat162_rn(v.x - __bfloat162float(h0.x),
                                              v.y - __bfloat162float(h0.y));
    __nv_bfloat162 l1 = __floats2bfloat162_rn(v.z - __bfloat162float(h1.x),
                                              v.w - __bfloat162float(h1.y));
    uint2 uh = make_uint2(*(uint32_t*)&h0, *(uint32_t*)&h1);
    uint2 ul = make_uint2(*(uint32_t*)&l0, *(uint32_t*)&l1);
    *(uint2*)(hi + (size_t)i * 4) = uh;
    *(uint2*)(lo + (size_t)i * 4) = ul;
}

// ---------------------------------------------------------------------------
// wsplit4: all four weights, z-indexed.  W[K,N] fp32 -> hi/lo bf16 [N][K]
// ---------------------------------------------------------------------------
__global__ __launch_bounds__(256)
void wsplit4(const float* __restrict__ Wq, const float* __restrict__ Wk,
             const float* __restrict__ Wv, const float* __restrict__ Wo,
             __nv_bfloat16* __restrict__ qhi, __nv_bfloat16* __restrict__ qlo,
             __nv_bfloat16* __restrict__ khi, __nv_bfloat16* __restrict__ klo,
             __nv_bfloat16* __restrict__ vhi, __nv_bfloat16* __restrict__ vlo,
             __nv_bfloat16* __restrict__ ohi, __nv_bfloat16* __restrict__ olo)
{
    __shared__ float tile[32][33];
    const int z = blockIdx.z;
    const float* W;  __nv_bfloat16 *hi, *lo;  int Ncols;
    if      (z == 0) { W = Wq; hi = qhi; lo = qlo; Ncols = D_MODEL; }
    else if (z == 1) { W = Wk; hi = khi; lo = klo; Ncols = KV_W; }
    else if (z == 2) { W = Wv; hi = vhi; lo = vlo; Ncols = KV_W; }
    else             { W = Wo; hi = ohi; lo = olo; Ncols = D_MODEL; }

    const int bx = blockIdx.x, by = blockIdx.y;
    if (bx * 32 >= Ncols) return;
    const int tx = threadIdx.x & 31, ty = threadIdx.x >> 5;

    #pragma unroll
    for (int i = 0; i < 32; i += 8)
        tile[ty + i][tx] = W[(size_t)(by * 32 + ty + i) * Ncols + bx * 32 + tx];
    __syncthreads();
    #pragma unroll
    for (int i = 0; i < 32; i += 8) {
        const int n = bx * 32 + ty + i;
        const int k = by * 32 + tx;
        float x = tile[tx][ty + i];
        __nv_bfloat16 h = __float2bfloat16_rn(x);
        hi[(size_t)n * GK + k] = h;
        lo[(size_t)n * GK + k] = __float2bfloat16_rn(x - __bfloat162float(h));
    }
}

// ---------------------------------------------------------------------------
// GEMM body: C[256x128 tile] = A @ B^T + bias.  A [M][K] hi/lo bf16,
// B [N][K] hi/lo bf16.  BK=32, 256 thr, 8 warps, warp tile 64x64.
// Smem stage layout: Ah(16K) Al(16K) Bh(8K) Bl(8K) = 48KB; 2 stages.
// MODE 0: float out; MODE 1: half out; MODE 2: half out * QSCALE.
// ---------------------------------------------------------------------------
#define GSTAGE 49152

template <int MODE>
__device__ __forceinline__
void gemm_body(const __nv_bfloat16* __restrict__ Ahi, const __nv_bfloat16* __restrict__ Alo,
               const __nv_bfloat16* __restrict__ Bhi, const __nv_bfloat16* __restrict__ Blo,
               const float* __restrict__ bias, void* __restrict__ Cout,
               int Ntot, int m0, int n0, uint32_t sb)
{
    const int tid  = threadIdx.x;
    const int lane = tid & 31;
    const int wid  = tid >> 5;
    const int wm   = (wid & 3) * 64;      // 4 m-warps * 64 = 256
    const int wn   = (wid >> 2) * 64;     // 2 n-warps * 64 = 128
    const int gg   = lane >> 2, tg = lane & 3;
    const int mi   = lane >> 3;

    float acc[4][8][4];
    #pragma unroll
    for (int a = 0; a < 4; a++)
        #pragma unroll
        for (int b = 0; b < 8; b++)
            #pragma unroll
            for (int c = 0; c < 4; c++) acc[a][b][c] = 0.f;

    auto load_stage = [&](int it) {
        const uint32_t st = sb + (it & 1) * GSTAGE;
        const int k0 = it * 32;
        // A: 256 rows x 4 segs, hi then lo  (4 + 4 cp.async per thread)
        #pragma unroll
        for (int t = 0; t < 4; t++) {
            const int f   = tid + t * 256;       // 0..1023
            const int row = f >> 2, c = f & 3;
            const uint32_t sw = row * 64 + ((c ^ ((row >> 1) & 3)) * 16);
            CP16(st + sw,         Ahi + (size_t)(m0 + row) * GK + k0 + c * 8);
            CP16(st + 16384 + sw, Alo + (size_t)(m0 + row) * GK + k0 + c * 8);
        }
        // B: 128 rows x 4 segs, hi then lo  (2 + 2 per thread)
        #pragma unroll
        for (int t = 0; t < 2; t++) {
            const int f   = tid + t * 256;       // 0..511
            const int row = f >> 2, c = f & 3;
            const uint32_t sw = row * 64 + ((c ^ ((row >> 1) & 3)) * 16);
            CP16(st + 32768 + sw, Bhi + (size_t)(n0 + row) * GK + k0 + c * 8);
            CP16(st + 40960 + sw, Blo + (size_t)(n0 + row) * GK + k0 + c * 8);
        }
    };

    load_stage(0);
    CPCOMMIT();

    const int NIT = GK / 32;
    for (int it = 0; it < NIT; it++) {
        if (it + 1 < NIT) { load_stage(it + 1); CPCOMMIT(); CPWAIT(1); }
        else              { CPWAIT(0); }
        __syncthreads();
        const uint32_t st = sb + (it & 1) * GSTAGE;

        #pragma unroll
        for (int s = 0; s < 2; s++) {
            uint32_t aH[4][4], aL[4][4];
            #pragma unroll
            for (int mt = 0; mt < 4; mt++) {
                const int r = wm + mt * 16 + (mi & 1) * 8 + (lane & 7);
                const int c = 2 * s + (mi >> 1);
                const uint32_t ad = st + r * 64 + ((c ^ ((r >> 1) & 3)) * 16);
                ldsm_x4(aH[mt][0], aH[mt][1], aH[mt][2], aH[mt][3], ad);
                ldsm_x4(aL[mt][0], aL[mt][1], aL[mt][2], aL[mt][3], ad + 16384);
            }
            uint32_t bH[8][2], bL[8][2];
            #pragma unroll
            for (int nt = 0; nt < 4; nt++) {
                const int r = wn + nt * 16 + (mi >> 1) * 8 + (lane & 7);
                const int c = 2 * s + (mi & 1);
                const uint32_t bd = st + 32768 + r * 64 + ((c ^ ((r >> 1) & 3)) * 16);
                ldsm_x4(bH[2*nt][0], bH[2*nt][1], bH[2*nt+1][0], bH[2*nt+1][1], bd);
                ldsm_x4(bL[2*nt][0], bL[2*nt][1], bL[2*nt+1][0], bL[2*nt+1][1], bd + 8192);
            }
            #pragma unroll
            for (int mt = 0; mt < 4; mt++)
                #pragma unroll
                for (int n = 0; n < 8; n++) {
                    mma_bf16(acc[mt][n], aH[mt], bH[n][0], bH[n][1]);
                    mma_bf16(acc[mt][n], aH[mt], bL[n][0], bL[n][1]);
                    mma_bf16(acc[mt][n], aL[mt], bH[n][0], bH[n][1]);
                }
        }
        __syncthreads();
    }

    // epilogue
    #pragma unroll
    for (int mt = 0; mt < 4; mt++)
        #pragma unroll
        for (int n = 0; n < 8; n++) {
            const int r0  = m0 + wm + mt * 16 + gg;
            const int col = n0 + wn + n * 8 + tg * 2;
            const float b0 = bias[col], b1 = bias[col + 1];
            if (MODE == 0) {
                float* C = (float*)Cout;
                *(float2*)(C + (size_t)r0 * Ntot + col) =
                    make_float2(acc[mt][n][0] + b0, acc[mt][n][1] + b1);
                *(float2*)(C + (size_t)(r0 + 8) * Ntot + col) =
                    make_float2(acc[mt][n][2] + b0, acc[mt][n][3] + b1);
            } else {
                const float sc = (MODE == 2) ? QSCALE : 1.0f;
                __half* C = (__half*)Cout;
                __half2 h0 = __floats2half2_rn((acc[mt][n][0] + b0) * sc,
                                               (acc[mt][n][1] + b1) * sc);
                __half2 h1 = __floats2half2_rn((acc[mt][n][2] + b0) * sc,
                                               (acc[mt][n][3] + b1) * sc);
                *(__half2*)(C + (size_t)r0 * Ntot + col) = h0;
                *(__half2*)(C + (size_t)(r0 + 8) * Ntot + col) = h1;
            }
        }
}

template <int MODE>
__global__ __launch_bounds__(256, 1)
void gemm_one(const __nv_bfloat16* __restrict__ Ahi, const __nv_bfloat16* __restrict__ Alo,
              const __nv_bfloat16* __restrict__ Bhi, const __nv_bfloat16* __restrict__ Blo,
              const float* __restrict__ bias, void* __restrict__ Cout, int Ntot)
{
    extern __shared__ char sm[];
    gemm_body<MODE>(Ahi, Alo, Bhi, Blo, bias, Cout, Ntot,
                    blockIdx.y * 256, blockIdx.x * 128, smem_u32(sm));
}

// fused K + V projections (blockIdx.z selects)
__global__ __launch_bounds__(256, 1)
void gemm_kv(const __nv_bfloat16* __restrict__ Khi, const __nv_bfloat16* __restrict__ Klo,
             const __nv_bfloat16* __restrict__ WKhi, const __nv_bfloat16* __restrict__ WKlo,
             const float* __restrict__ bk, __half* __restrict__ kh,
             const __nv_bfloat16* __restrict__ Vhi, const __nv_bfloat16* __restrict__ Vlo,
             const __nv_bfloat16* __restrict__ WVhi, const __nv_bfloat16* __restrict__ WVlo,
             const float* __restrict__ bv, __half* __restrict__ vh)
{
    extern __shared__ char sm[];
    const uint32_t sb = smem_u32(sm);
    if (blockIdx.z == 0)
        gemm_body<1>(Khi, Klo, WKhi, WKlo, bk, kh, KV_W,
                     blockIdx.y * 256, blockIdx.x * 128, sb);
    else
        gemm_body<1>(Vhi, Vlo, WVhi, WVlo, bv, vh, KV_W,
                     blockIdx.y * 256, blockIdx.x * 128, sb);
}

// ---------------------------------------------------------------------------
// fp16 HMMA causal flash attention.  64 q-rows x 64 kv per tile, 4 warps.
// ---------------------------------------------------------------------------
__global__ __launch_bounds__(128)
void flash(const __half* __restrict__ qbuf, const __half* __restrict__ kbuf,
           const __half* __restrict__ vbuf, float* __restrict__ obuf)
{
    __shared__ __align__(16) __half sQ[64 * 64];
    __shared__ __align__(16) __half sK[2][64 * 64];
    __shared__ __align__(16) __half sV[2][64 * 64];

    const int qt   = (int)gridDim.x - 1 - (int)blockIdx.x;
    const int h    = blockIdx.y;
    const int g    = h >> 2;
    const int tid  = threadIdx.x;
    const int warp = tid >> 5, lane = tid & 31;
    const int gg   = lane >> 2, tg = lane & 3;
    const int mi   = lane >> 3;
    const int q0   = qt * 64;

    const uint32_t qb  = smem_u32(sQ);
    const uint32_t kb0 = smem_u32(sK);
    const uint32_t vb0 = smem_u32(sV);

    #pragma unroll
    for (int i = 0; i < 4; i++) {
        const int f = tid + i * 128;
        const int r = f >> 3, c = f & 7;
        CP16(qb + r * 128 + ((c ^ (r & 7)) * 16),
             qbuf + (size_t)(q0 + r) * D_MODEL + h * 64 + c * 8);
    }
    auto loadKV = [&](int kt) {
        const uint32_t ko = kb0 + (kt & 1) * 8192;
        const uint32_t vo = vb0 + (kt & 1) * 8192;
        #pragma unroll
        for (int i = 0; i < 4; i++) {
            const int f = tid + i * 128;
            const int r = f >> 3, c = f & 7;
            const size_t src = (size_t)(kt * 64 + r) * KV_W + g * 64 + c * 8;
            const uint32_t d = r * 128 + ((c ^ (r & 7)) * 16);
            CP16(ko + d, kbuf + src);
            CP16(vo + d, vbuf + src);
        }
    };
    loadKV(0);
    CPCOMMIT();
    CPWAIT(0);
    __syncthreads();

    uint32_t qa[4][4];
    {
        const int r = warp * 16 + (mi & 1) * 8 + (lane & 7);
        #pragma unroll
        for (int s = 0; s < 4; s++) {
            const int c = 2 * s + (mi >> 1);
            ldsm_x4(qa[s][0], qa[s][1], qa[s][2], qa[s][3],
                    qb + r * 128 + ((c ^ (r & 7)) * 16));
        }
    }

    float o[8][4];
    #pragma unroll
    for (int n = 0; n < 8; n++)
        #pragma unroll
        for (int c = 0; c < 4; c++) o[n][c] = 0.f;
    float m0v = -1e30f, m1v = -1e30f, l0 = 0.f, l1 = 0.f;
    const int r0g = q0 + warp * 16 + gg;
    const int r1g = r0g + 8;

    for (int kt = 0; kt <= qt; kt++) {
        if (kt < qt) { loadKV(kt + 1); CPCOMMIT(); CPWAIT(1); }
        else         { CPWAIT(0); }
        __syncthreads();
        const uint32_t ko = kb0 + (kt & 1) * 8192;
        const uint32_t vo = vb0 + (kt & 1) * 8192;

        float sc[8][4];
        #pragma unroll
        for (int n = 0; n < 8; n++)
            #pragma unroll
            for (int c = 0; c < 4; c++) sc[n][c] = 0.f;

        #pragma unroll
        for (int s = 0; s < 4; s++)
            #pragma unroll
            for (int nt = 0; nt < 4; nt++) {
                const int r = nt * 16 + (mi >> 1) * 8 + (lane & 7);
                const int c = 2 * s + (mi & 1);
                uint32_t b0r, b1r, b2r, b3r;
                ldsm_x4(b0r, b1r, b2r, b3r, ko + r * 128 + ((c ^ (r & 7)) * 16));
                mma_f16(sc[2 * nt],     qa[s], b0r, b1r);
                mma_f16(sc[2 * nt + 1], qa[s], b2r, b3r);
            }

        if (kt == qt) {
            #pragma unroll
            for (int n = 0; n < 8; n++) {
                const int col = kt * 64 + n * 8 + tg * 2;
                if (col     > r0g) sc[n][0] = -1e30f;
                if (col + 1 > r0g) sc[n][1] = -1e30f;
                if (col     > r1g) sc[n][2] = -1e30f;
                if (col + 1 > r1g) sc[n][3] = -1e30f;
            }
        }

        float mx0 = -1e30f, mx1 = -1e30f;
        #pragma unroll
        for (int n = 0; n < 8; n++) {
            mx0 = fmaxf(mx0, fmaxf(sc[n][0], sc[n][1]));
            mx1 = fmaxf(mx1, fmaxf(sc[n][2], sc[n][3]));
        }
        mx0 = fmaxf(mx0, __shfl_xor_sync(0xffffffffu, mx0, 1));
        mx0 = fmaxf(mx0, __shfl_xor_sync(0xffffffffu, mx0, 2));
        mx1 = fmaxf(mx1, __shfl_xor_sync(0xffffffffu, mx1, 1));
        mx1 = fmaxf(mx1, __shfl_xor_sync(0xffffffffu, mx1, 2));
        const float mn0 = fmaxf(m0v, mx0), mn1 = fmaxf(m1v, mx1);
        const float c0 = exp2f(m0v - mn0), c1 = exp2f(m1v - mn1);
        m0v = mn0; m1v = mn1;

        float ps0 = 0.f, ps1 = 0.f;
        #pragma unroll
        for (int n = 0; n < 8; n++) {
            sc[n][0] = exp2f(sc[n][0] - mn0);
            sc[n][1] = exp2f(sc[n][1] - mn0);
            sc[n][2] = exp2f(sc[n][2] - mn1);
            sc[n][3] = exp2f(sc[n][3] - mn1);
            ps0 += sc[n][0] + sc[n][1];
            ps1 += sc[n][2] + sc[n][3];
        }
        l0 = l0 * c0 + ps0;
        l1 = l1 * c1 + ps1;
        #pragma unroll
        for (int n = 0; n < 8; n++) {
            o[n][0] *= c0; o[n][1] *= c0;
            o[n][2] *= c1; o[n][3] *= c1;
        }

        uint32_t pa[4][4];
        #pragma unroll
        for (int s = 0; s < 4; s++) {
            __half2 p0 = __floats2half2_rn(sc[2*s][0],   sc[2*s][1]);
            __half2 p1 = __floats2half2_rn(sc[2*s][2],   sc[2*s][3]);
            __half2 p2 = __floats2half2_rn(sc[2*s+1][0], sc[2*s+1][1]);
            __half2 p3 = __floats2half2_rn(sc[2*s+1][2], sc[2*s+1][3]);
            pa[s][0] = *(uint32_t*)&p0;
            pa[s][1] = *(uint32_t*)&p1;
            pa[s][2] = *(uint32_t*)&p2;
            pa[s][3] = *(uint32_t*)&p3;
        }

        #pragma unroll
        for (int s = 0; s < 4; s++)
            #pragma unroll
            for (int nt = 0; nt < 4; nt++) {
                const int r = s * 16 + (mi & 1) * 8 + (lane & 7);
                const int c = 2 * nt + (mi >> 1);
                uint32_t b0r, b1r, b2r, b3r;
                ldsm_x4t(b0r, b1r, b2r, b3r, vo + r * 128 + ((c ^ (r & 7)) * 16));
                mma_f16(o[2 * nt],     pa[s], b0r, b1r);
                mma_f16(o[2 * nt + 1], pa[s], b2r, b3r);
            }
        __syncthreads();
    }

    l0 += __shfl_xor_sync(0xffffffffu, l0, 1);
    l0 += __shfl_xor_sync(0xffffffffu, l0, 2);
    l1 += __shfl_xor_sync(0xffffffffu, l1, 1);
    l1 += __shfl_xor_sync(0xffffffffu, l1, 2);
    const float i0 = 1.f / l0, i1 = 1.f / l1;

    #pragma unroll
    for (int n = 0; n < 8; n++) {
        const int col = h * 64 + n * 8 + tg * 2;
        *(float2*)(obuf + (size_t)r0g * D_MODEL + col) =
            make_float2(o[n][0] * i0, o[n][1] * i0);
        *(float2*)(obuf + (size_t)r1g * D_MODEL + col) =
            make_float2(o[n][2] * i1, o[n][3] * i1);
    }
}

// ---------------------------------------------------------------------------
// Launch
// ---------------------------------------------------------------------------
extern "C" void kernel_launch(void* const* d_in, const int* in_sizes, int n_in,
                              void* d_out, int out_size)
{
    const float* queries = (const float*)d_in[0];
    const float* keys    = (const float*)d_in[1];
    const float* values  = (const float*)d_in[2];
    const float* Wq      = (const float*)d_in[3];
    const float* bq      = (const float*)d_in[4];
    const float* Wk      = (const float*)d_in[5];
    const float* bk      = (const float*)d_in[6];
    const float* Wv      = (const float*)d_in[7];
    const float* bv      = (const float*)d_in[8];
    const float* Wo      = (const float*)d_in[9];
    const float* bo      = (const float*)d_in[10];
    float*       out     = (float*)d_out;

    __half *qh, *kh, *vh;  float *attn;
    __nv_bfloat16 *ahi, *alo, *bhi, *blo, *chi, *clo;
    __nv_bfloat16 *wqh, *wql, *wkh, *wkl, *wvh, *wvl, *woh, *wol;
    cudaGetSymbolAddress((void**)&qh,  g_qh);
    cudaGetSymbolAddress((void**)&kh,  g_kh);
    cudaGetSymbolAddress((void**)&vh,  g_vh);
    cudaGetSymbolAddress((void**)&attn, g_attn);
    cudaGetSymbolAddress((void**)&ahi, g_ahi);
    cudaGetSymbolAddress((void**)&alo, g_alo);
    cudaGetSymbolAddress((void**)&bhi, g_bhi);
    cudaGetSymbolAddress((void**)&blo, g_blo);
    cudaGetSymbolAddress((void**)&chi, g_chi);
    cudaGetSymbolAddress((void**)&clo, g_clo);
    cudaGetSymbolAddress((void**)&wqh, g_wq_hi);
    cudaGetSymbolAddress((void**)&wql, g_wq_lo);
    cudaGetSymbolAddress((void**)&wkh, g_wk_hi);
    cudaGetSymbolAddress((void**)&wkl, g_wk_lo);
    cudaGetSymbolAddress((void**)&wvh, g_wv_hi);
    cudaGetSymbolAddress((void**)&wvl, g_wv_lo);
    cudaGetSymbolAddress((void**)&woh, g_wo_hi);
    cudaGetSymbolAddress((void**)&wol, g_wo_lo);

    cudaFuncSetAttribute(gemm_one<0>, cudaFuncAttributeMaxDynamicSharedMemorySize, 2 * GSTAGE);
    cudaFuncSetAttribute(gemm_one<2>, cudaFuncAttributeMaxDynamicSharedMemorySize, 2 * GSTAGE);
    cudaFuncSetAttribute(gemm_kv,     cudaFuncAttributeMaxDynamicSharedMemorySize, 2 * GSTAGE);

    const int NELEM4 = S_LEN * D_MODEL / 4;

    // weight prep (all four, one launch)
    wsplit4<<<dim3(D_MODEL / 32, GK / 32, 4), 256>>>(
        Wq, Wk, Wv, Wo, wqh, wql, wkh, wkl, wvh, wvl, woh, wol);

    // activation splits
    asplit<<<NELEM4 / 256, 256>>>((const float4*)queries, ahi, alo);
    asplit<<<NELEM4 / 256, 256>>>((const float4*)keys,    bhi, blo);
    asplit<<<NELEM4 / 256, 256>>>((const float4*)values,  chi, clo);

    // Q projection  (half out, pre-scaled)
    gemm_one<2><<<dim3(D_MODEL / 128, S_LEN / 256), 256, 2 * GSTAGE>>>(
        ahi, alo, wqh, wql, bq, qh, D_MODEL);

    // K + V projections fused (half out)
    gemm_kv<<<dim3(KV_W / 128, S_LEN / 256, 2), 256, 2 * GSTAGE>>>(
        bhi, blo, wkh, wkl, bk, kh,
        chi, clo, wvh, wvl, bv, vh);

    // causal GQA flash attention (fp16 HMMA)
    flash<<<dim3(S_LEN / 64, H_Q), 128>>>(qh, kh, vh, attn);

    // output projection (float out)
    asplit<<<NELEM4 / 256, 256>>>((const float4*)attn, ahi, alo);
    gemm_one<0><<<dim3(D_MODEL / 128, S_LEN / 256), 256, 2 * GSTAGE>>>(
        ahi, alo, woh, wol, bo, out, D_MODEL);
}

// round 5
// speedup vs baseline: 5.0614x; 1.0776x over previous
#include <cuda_runtime.h>
#include <cuda_bf16.h>
#include <cuda_fp16.h>
#include <cstdint>

// ===========================================================================
// GQA layer, sm_103 baseline-PTX path: mma.sync (HMMA) everywhere.
//   - projections: bf16 split-2 GEMM via mma.sync.m16n8k16
//       CTA tile 256x128, warp tile 64x64, BK=32, 3-stage cp.async, 1 sync/it
//   - attention:   fp16 FA-2, q-tile 128/CTA, warp tile 32x64, bf16-split out
// ===========================================================================

#define S_LEN   2048
#define D_MODEL 2048
#define H_Q     32
#define KV_W    512
#define GK      2048
#define QSCALE  0.1803368801111244f   // 0.125 * log2(e)

// ------------------------------ scratch ------------------------------------
__device__ __align__(16) __half g_qh[S_LEN * D_MODEL];
__device__ __align__(16) __half g_kh[S_LEN * KV_W];
__device__ __align__(16) __half g_vh[S_LEN * KV_W];

// split activations: A (queries, then attn-out), B (keys), C (values)
__device__ __align__(16) __nv_bfloat16 g_ahi[S_LEN * D_MODEL];
__device__ __align__(16) __nv_bfloat16 g_alo[S_LEN * D_MODEL];
__device__ __align__(16) __nv_bfloat16 g_bhi[S_LEN * D_MODEL];
__device__ __align__(16) __nv_bfloat16 g_blo[S_LEN * D_MODEL];
__device__ __align__(16) __nv_bfloat16 g_chi[S_LEN * D_MODEL];
__device__ __align__(16) __nv_bfloat16 g_clo[S_LEN * D_MODEL];

// transposed + split weights, [N][K]
__device__ __align__(16) __nv_bfloat16 g_wq_hi[D_MODEL * GK];
__device__ __align__(16) __nv_bfloat16 g_wq_lo[D_MODEL * GK];
__device__ __align__(16) __nv_bfloat16 g_wk_hi[KV_W * GK];
__device__ __align__(16) __nv_bfloat16 g_wk_lo[KV_W * GK];
__device__ __align__(16) __nv_bfloat16 g_wv_hi[KV_W * GK];
__device__ __align__(16) __nv_bfloat16 g_wv_lo[KV_W * GK];
__device__ __align__(16) __nv_bfloat16 g_wo_hi[D_MODEL * GK];
__device__ __align__(16) __nv_bfloat16 g_wo_lo[D_MODEL * GK];

// ------------------------------ helpers ------------------------------------
__device__ __forceinline__ uint32_t smem_u32(const void* p) {
    uint32_t a;
    asm("{ .reg .u64 t; cvta.to.shared.u64 t, %1; cvt.u32.u64 %0, t; }"
        : "=r"(a) : "l"(p));
    return a;
}

#define CP16(dst, src) \
    asm volatile("cp.async.cg.shared.global [%0], [%1], 16;" \
                 :: "r"(dst), "l"(src))
#define CPCOMMIT() asm volatile("cp.async.commit_group;" ::: "memory")
#define CPWAIT(n)  asm volatile("cp.async.wait_group %0;" :: "n"(n) : "memory")

__device__ __forceinline__ void ldsm_x4(uint32_t& r0, uint32_t& r1,
                                        uint32_t& r2, uint32_t& r3, uint32_t a) {
    asm volatile("ldmatrix.sync.aligned.m8n8.x4.shared.b16 {%0,%1,%2,%3}, [%4];"
                 : "=r"(r0), "=r"(r1), "=r"(r2), "=r"(r3) : "r"(a));
}
__device__ __forceinline__ void ldsm_x4t(uint32_t& r0, uint32_t& r1,
                                         uint32_t& r2, uint32_t& r3, uint32_t a) {
    asm volatile("ldmatrix.sync.aligned.m8n8.x4.trans.shared.b16 {%0,%1,%2,%3}, [%4];"
                 : "=r"(r0), "=r"(r1), "=r"(r2), "=r"(r3) : "r"(a));
}

__device__ __forceinline__ void mma_bf16(float* c, const uint32_t* a,
                                         uint32_t b0, uint32_t b1) {
    asm volatile("mma.sync.aligned.m16n8k16.row.col.f32.bf16.bf16.f32 "
                 "{%0,%1,%2,%3}, {%4,%5,%6,%7}, {%8,%9}, {%0,%1,%2,%3};"
                 : "+f"(c[0]), "+f"(c[1]), "+f"(c[2]), "+f"(c[3])
                 : "r"(a[0]), "r"(a[1]), "r"(a[2]), "r"(a[3]), "r"(b0), "r"(b1));
}
__device__ __forceinline__ void mma_f16(float* c, const uint32_t* a,
                                        uint32_t b0, uint32_t b1) {
    asm volatile("mma.sync.aligned.m16n8k16.row.col.f32.f16.f16.f32 "
                 "{%0,%1,%2,%3}, {%4,%5,%6,%7}, {%8,%9}, {%0,%1,%2,%3};"
                 : "+f"(c[0]), "+f"(c[1]), "+f"(c[2]), "+f"(c[3])
                 : "r"(a[0]), "r"(a[1]), "r"(a[2]), "r"(a[3]), "r"(b0), "r"(b1));
}

// ---------------------------------------------------------------------------
// asplit3: three fp32 activation tensors -> bf16 hi/lo, z-indexed
// ---------------------------------------------------------------------------
__global__ __launch_bounds__(256)
void asplit3(const float4* __restrict__ Q, const float4* __restrict__ K,
             const float4* __restrict__ V,
             __nv_bfloat16* __restrict__ ahi, __nv_bfloat16* __restrict__ alo,
             __nv_bfloat16* __restrict__ bhi, __nv_bfloat16* __restrict__ blo,
             __nv_bfloat16* __restrict__ chi, __nv_bfloat16* __restrict__ clo)
{
    const int z = blockIdx.y;
    const float4* A;  __nv_bfloat16 *hi, *lo;
    if      (z == 0) { A = Q; hi = ahi; lo = alo; }
    else if (z == 1) { A = K; hi = bhi; lo = blo; }
    else             { A = V; hi = chi; lo = clo; }

    const int i = blockIdx.x * 256 + threadIdx.x;
    float4 v = A[i];
    __nv_bfloat162 h0 = __floats2bfloat162_rn(v.x, v.y);
    __nv_bfloat162 h1 = __floats2bfloat162_rn(v.z, v.w);
    __nv_bfloat162 l0 = __floats2bfloat162_rn(v.x - __bfloat162float(h0.x),
                                              v.y - __bfloat162float(h0.y));
    __nv_bfloat162 l1 = __floats2bfloat162_rn(v.z - __bfloat162float(h1.x),
                                              v.w - __bfloat162float(h1.y));
    uint2 uh = make_uint2(*(uint32_t*)&h0, *(uint32_t*)&h1);
    uint2 ul = make_uint2(*(uint32_t*)&l0, *(uint32_t*)&l1);
    *(uint2*)(hi + (size_t)i * 4) = uh;
    *(uint2*)(lo + (size_t)i * 4) = ul;
}

// ---------------------------------------------------------------------------
// wsplit4: all four weights, z-indexed.  W[K,N] fp32 -> hi/lo bf16 [N][K]
// ---------------------------------------------------------------------------
__global__ __launch_bounds__(256)
void wsplit4(const float* __restrict__ Wq, const float* __restrict__ Wk,
             const float* __restrict__ Wv, const float* __restrict__ Wo,
             __nv_bfloat16* __restrict__ qhi, __nv_bfloat16* __restrict__ qlo,
             __nv_bfloat16* __restrict__ khi, __nv_bfloat16* __restrict__ klo,
             __nv_bfloat16* __restrict__ vhi, __nv_bfloat16* __restrict__ vlo,
             __nv_bfloat16* __restrict__ ohi, __nv_bfloat16* __restrict__ olo)
{
    __shared__ float tile[32][33];
    const int z = blockIdx.z;
    const float* W;  __nv_bfloat16 *hi, *lo;  int Ncols;
    if      (z == 0) { W = Wq; hi = qhi; lo = qlo; Ncols = D_MODEL; }
    else if (z == 1) { W = Wk; hi = khi; lo = klo; Ncols = KV_W; }
    else if (z == 2) { W = Wv; hi = vhi; lo = vlo; Ncols = KV_W; }
    else             { W = Wo; hi = ohi; lo = olo; Ncols = D_MODEL; }

    const int bx = blockIdx.x, by = blockIdx.y;
    if (bx * 32 >= Ncols) return;
    const int tx = threadIdx.x & 31, ty = threadIdx.x >> 5;

    #pragma unroll
    for (int i = 0; i < 32; i += 8)
        tile[ty + i][tx] = W[(size_t)(by * 32 + ty + i) * Ncols + bx * 32 + tx];
    __syncthreads();
    #pragma unroll
    for (int i = 0; i < 32; i += 8) {
        const int n = bx * 32 + ty + i;
        const int k = by * 32 + tx;
        float x = tile[tx][ty + i];
        __nv_bfloat16 h = __float2bfloat16_rn(x);
        hi[(size_t)n * GK + k] = h;
        lo[(size_t)n * GK + k] = __float2bfloat16_rn(x - __bfloat162float(h));
    }
}

// ---------------------------------------------------------------------------
// GEMM body: C[256x128 tile] = A @ B^T + bias.  bf16 split-2 (3 passes).
// BK=32, 256 thr, 8 warps, warp tile 64x64.  3-stage cp.async, 1 sync/iter.
// Stage: Ah(16K) Al(16K) Bh(8K) Bl(8K) = 48KB.
// MODE 0: float out; MODE 1: half out; MODE 2: half out * QSCALE.
// ---------------------------------------------------------------------------
#define GSTAGE 49152

template <int MODE>
__device__ __forceinline__
void gemm_body(const __nv_bfloat16* __restrict__ Ahi, const __nv_bfloat16* __restrict__ Alo,
               const __nv_bfloat16* __restrict__ Bhi, const __nv_bfloat16* __restrict__ Blo,
               const float* __restrict__ bias, void* __restrict__ Cout,
               int Ntot, int m0, int n0, uint32_t sb)
{
    const int tid  = threadIdx.x;
    const int lane = tid & 31;
    const int wid  = tid >> 5;
    const int wm   = (wid & 3) * 64;
    const int wn   = (wid >> 2) * 64;
    const int gg   = lane >> 2, tg = lane & 3;
    const int mi   = lane >> 3;

    float acc[4][8][4];
    #pragma unroll
    for (int a = 0; a < 4; a++)
        #pragma unroll
        for (int b = 0; b < 8; b++)
            #pragma unroll
            for (int c = 0; c < 4; c++) acc[a][b][c] = 0.f;

    auto load_stage = [&](int it) {
        const uint32_t st = sb + (it % 3) * GSTAGE;
        const int k0 = it * 32;
        #pragma unroll
        for (int t = 0; t < 4; t++) {
            const int f   = tid + t * 256;
            const int row = f >> 2, c = f & 3;
            const uint32_t sw = row * 64 + ((c ^ ((row >> 1) & 3)) * 16);
            CP16(st + sw,         Ahi + (size_t)(m0 + row) * GK + k0 + c * 8);
            CP16(st + 16384 + sw, Alo + (size_t)(m0 + row) * GK + k0 + c * 8);
        }
        #pragma unroll
        for (int t = 0; t < 2; t++) {
            const int f   = tid + t * 256;
            const int row = f >> 2, c = f & 3;
            const uint32_t sw = row * 64 + ((c ^ ((row >> 1) & 3)) * 16);
            CP16(st + 32768 + sw, Bhi + (size_t)(n0 + row) * GK + k0 + c * 8);
            CP16(st + 40960 + sw, Blo + (size_t)(n0 + row) * GK + k0 + c * 8);
        }
    };

    load_stage(0); CPCOMMIT();
    load_stage(1); CPCOMMIT();

    const int NIT = GK / 32;
    for (int it = 0; it < NIT; it++) {
        if (it + 1 < NIT) { CPWAIT(1); } else { CPWAIT(0); }
        __syncthreads();
        const uint32_t st = sb + (it % 3) * GSTAGE;

        #pragma unroll
        for (int s = 0; s < 2; s++) {
            uint32_t aH[4][4], aL[4][4];
            #pragma unroll
            for (int mt = 0; mt < 4; mt++) {
                const int r = wm + mt * 16 + (mi & 1) * 8 + (lane & 7);
                const int c = 2 * s + (mi >> 1);
                const uint32_t ad = st + r * 64 + ((c ^ ((r >> 1) & 3)) * 16);
                ldsm_x4(aH[mt][0], aH[mt][1], aH[mt][2], aH[mt][3], ad);
                ldsm_x4(aL[mt][0], aL[mt][1], aL[mt][2], aL[mt][3], ad + 16384);
            }
            uint32_t bH[8][2], bL[8][2];
            #pragma unroll
            for (int nt = 0; nt < 4; nt++) {
                const int r = wn + nt * 16 + (mi >> 1) * 8 + (lane & 7);
                const int c = 2 * s + (mi & 1);
                const uint32_t bd = st + 32768 + r * 64 + ((c ^ ((r >> 1) & 3)) * 16);
                ldsm_x4(bH[2*nt][0], bH[2*nt][1], bH[2*nt+1][0], bH[2*nt+1][1], bd);
                ldsm_x4(bL[2*nt][0], bL[2*nt][1], bL[2*nt+1][0], bL[2*nt+1][1], bd + 8192);
            }
            #pragma unroll
            for (int mt = 0; mt < 4; mt++)
                #pragma unroll
                for (int n = 0; n < 8; n++) {
                    mma_bf16(acc[mt][n], aH[mt], bH[n][0], bH[n][1]);
                    mma_bf16(acc[mt][n], aH[mt], bL[n][0], bL[n][1]);
                    mma_bf16(acc[mt][n], aL[mt], bH[n][0], bH[n][1]);
                }
        }
        if (it + 2 < NIT) { load_stage(it + 2); CPCOMMIT(); }
    }

    #pragma unroll
    for (int mt = 0; mt < 4; mt++)
        #pragma unroll
        for (int n = 0; n < 8; n++) {
            const int r0  = m0 + wm + mt * 16 + gg;
            const int col = n0 + wn + n * 8 + tg * 2;
            const float b0 = bias[col], b1 = bias[col + 1];
            if (MODE == 0) {
                float* C = (float*)Cout;
                *(float2*)(C + (size_t)r0 * Ntot + col) =
                    make_float2(acc[mt][n][0] + b0, acc[mt][n][1] + b1);
                *(float2*)(C + (size_t)(r0 + 8) * Ntot + col) =
                    make_float2(acc[mt][n][2] + b0, acc[mt][n][3] + b1);
            } else {
                const float sc = (MODE == 2) ? QSCALE : 1.0f;
                __half* C = (__half*)Cout;
                __half2 h0 = __floats2half2_rn((acc[mt][n][0] + b0) * sc,
                                               (acc[mt][n][1] + b1) * sc);
                __half2 h1 = __floats2half2_rn((acc[mt][n][2] + b0) * sc,
                                               (acc[mt][n][3] + b1) * sc);
                *(__half2*)(C + (size_t)r0 * Ntot + col) = h0;
                *(__half2*)(C + (size_t)(r0 + 8) * Ntot + col) = h1;
            }
        }
}

template <int MODE>
__global__ __launch_bounds__(256, 1)
void gemm_one(const __nv_bfloat16* __restrict__ Ahi, const __nv_bfloat16* __restrict__ Alo,
              const __nv_bfloat16* __restrict__ Bhi, const __nv_bfloat16* __restrict__ Blo,
              const float* __restrict__ bias, void* __restrict__ Cout, int Ntot)
{
    extern __shared__ char sm[];
    gemm_body<MODE>(Ahi, Alo, Bhi, Blo, bias, Cout, Ntot,
                    blockIdx.y * 256, blockIdx.x * 128, smem_u32(sm));
}

__global__ __launch_bounds__(256, 1)
void gemm_kv(const __nv_bfloat16* __restrict__ Khi, const __nv_bfloat16* __restrict__ Klo,
             const __nv_bfloat16* __restrict__ WKhi, const __nv_bfloat16* __restrict__ WKlo,
             const float* __restrict__ bk, __half* __restrict__ kh,
             const __nv_bfloat16* __restrict__ Vhi, const __nv_bfloat16* __restrict__ Vlo,
             const __nv_bfloat16* __restrict__ WVhi, const __nv_bfloat16* __restrict__ WVlo,
             const float* __restrict__ bv, __half* __restrict__ vh)
{
    extern __shared__ char sm[];
    const uint32_t sb = smem_u32(sm);
    if (blockIdx.z == 0)
        gemm_body<1>(Khi, Klo, WKhi, WKlo, bk, kh, KV_W,
                     blockIdx.y * 256, blockIdx.x * 128, sb);
    else
        gemm_body<1>(Vhi, Vlo, WVhi, WVlo, bv, vh, KV_W,
                     blockIdx.y * 256, blockIdx.x * 128, sb);
}

// ---------------------------------------------------------------------------
// fp16 HMMA causal flash attention.  q-tile 128/CTA, 4 warps (32 q-rows each),
// kv tile 64, double-buffered.  Output written as bf16 hi/lo split.
// ---------------------------------------------------------------------------
__global__ __launch_bounds__(128)
void flash(const __half* __restrict__ qbuf, const __half* __restrict__ kbuf,
           const __half* __restrict__ vbuf,
           __nv_bfloat16* __restrict__ ohi, __nv_bfloat16* __restrict__ olo)
{
    __shared__ __align__(16) __half sQ[128 * 64];
    __shared__ __align__(16) __half sK[2][64 * 64];
    __shared__ __align__(16) __half sV[2][64 * 64];

    const int qt   = (int)gridDim.x - 1 - (int)blockIdx.x;
    const int h    = blockIdx.y;
    const int g    = h >> 2;
    const int tid  = threadIdx.x;
    const int warp = tid >> 5, lane = tid & 31;
    const int gg   = lane >> 2, tg = lane & 3;
    const int mi   = lane >> 3;
    const int q0   = qt * 128;
    const int wrow = q0 + warp * 32;

    const uint32_t qb  = smem_u32(sQ);
    const uint32_t kb0 = smem_u32(sK);
    const uint32_t vb0 = smem_u32(sV);

    // load Q tile (128 rows x 64)
    #pragma unroll
    for (int i = 0; i < 8; i++) {
        const int f = tid + i * 128;
        const int r = f >> 3, c = f & 7;
        CP16(qb + r * 128 + ((c ^ (r & 7)) * 16),
             qbuf + (size_t)(q0 + r) * D_MODEL + h * 64 + c * 8);
    }
    auto loadKV = [&](int kt) {
        const uint32_t ko = kb0 + (kt & 1) * 8192;
        const uint32_t vo = vb0 + (kt & 1) * 8192;
        #pragma unroll
        for (int i = 0; i < 4; i++) {
            const int f = tid + i * 128;
            const int r = f >> 3, c = f & 7;
            const size_t src = (size_t)(kt * 64 + r) * KV_W + g * 64 + c * 8;
            const uint32_t d = r * 128 + ((c ^ (r & 7)) * 16);
            CP16(ko + d, kbuf + src);
            CP16(vo + d, vbuf + src);
        }
    };
    loadKV(0);
    CPCOMMIT();
    CPWAIT(0);
    __syncthreads();

    // Q fragments: [s][mt][4]
    uint32_t qa[4][2][4];
    #pragma unroll
    for (int mt = 0; mt < 2; mt++) {
        const int r = warp * 32 + mt * 16 + (mi & 1) * 8 + (lane & 7);
        #pragma unroll
        for (int s = 0; s < 4; s++) {
            const int c = 2 * s + (mi >> 1);
            ldsm_x4(qa[s][mt][0], qa[s][mt][1], qa[s][mt][2], qa[s][mt][3],
                    qb + r * 128 + ((c ^ (r & 7)) * 16));
        }
    }

    float o[2][8][4];
    #pragma unroll
    for (int mt = 0; mt < 2; mt++)
        #pragma unroll
        for (int n = 0; n < 8; n++)
            #pragma unroll
            for (int c = 0; c < 4; c++) o[mt][n][c] = 0.f;
    float mM[2][2] = {{-1e30f, -1e30f}, {-1e30f, -1e30f}};
    float lL[2][2] = {{0.f, 0.f}, {0.f, 0.f}};

    const int KT = 2 * qt + 2;
    for (int kt = 0; kt < KT; kt++) {
        if (kt + 1 < KT) { loadKV(kt + 1); CPCOMMIT(); CPWAIT(1); }
        else             { CPWAIT(0); }
        __syncthreads();
        const uint32_t ko = kb0 + (kt & 1) * 8192;
        const uint32_t vo = vb0 + (kt & 1) * 8192;

        // ---- S = Q K^T ----
        float sc[2][8][4];
        #pragma unroll
        for (int mt = 0; mt < 2; mt++)
            #pragma unroll
            for (int n = 0; n < 8; n++)
                #pragma unroll
                for (int c = 0; c < 4; c++) sc[mt][n][c] = 0.f;

        #pragma unroll
        for (int s = 0; s < 4; s++) {
            uint32_t bfr[8][2];
            #pragma unroll
            for (int nt = 0; nt < 4; nt++) {
                const int r = nt * 16 + (mi >> 1) * 8 + (lane & 7);
                const int c = 2 * s + (mi & 1);
                ldsm_x4(bfr[2*nt][0], bfr[2*nt][1], bfr[2*nt+1][0], bfr[2*nt+1][1],
                        ko + r * 128 + ((c ^ (r & 7)) * 16));
            }
            #pragma unroll
            for (int mt = 0; mt < 2; mt++)
                #pragma unroll
                for (int n = 0; n < 8; n++)
                    mma_f16(sc[mt][n], qa[s][mt], bfr[n][0], bfr[n][1]);
        }

        // causal mask (only tiles overlapping this warp's diagonal)
        if (kt * 64 + 63 > wrow) {
            #pragma unroll
            for (int mt = 0; mt < 2; mt++) {
                const int r0 = wrow + mt * 16 + gg;
                const int r1 = r0 + 8;
                #pragma unroll
                for (int n = 0; n < 8; n++) {
                    const int col = kt * 64 + n * 8 + tg * 2;
                    if (col     > r0) sc[mt][n][0] = -1e30f;
                    if (col + 1 > r0) sc[mt][n][1] = -1e30f;
                    if (col     > r1) sc[mt][n][2] = -1e30f;
                    if (col + 1 > r1) sc[mt][n][3] = -1e30f;
                }
            }
        }

        // ---- online softmax (exp2 domain) ----
        uint32_t pa[2][4][4];
        #pragma unroll
        for (int mt = 0; mt < 2; mt++) {
            float mx0 = -1e30f, mx1 = -1e30f;
            #pragma unroll
            for (int n = 0; n < 8; n++) {
                mx0 = fmaxf(mx0, fmaxf(sc[mt][n][0], sc[mt][n][1]));
                mx1 = fmaxf(mx1, fmaxf(sc[mt][n][2], sc[mt][n][3]));
            }
            mx0 = fmaxf(mx0, __shfl_xor_sync(0xffffffffu, mx0, 1));
            mx0 = fmaxf(mx0, __shfl_xor_sync(0xffffffffu, mx0, 2));
            mx1 = fmaxf(mx1, __shfl_xor_sync(0xffffffffu, mx1, 1));
            mx1 = fmaxf(mx1, __shfl_xor_sync(0xffffffffu, mx1, 2));
            const float mn0 = fmaxf(mM[mt][0], mx0);
            const float mn1 = fmaxf(mM[mt][1], mx1);
            const float c0 = exp2f(mM[mt][0] - mn0);
            const float c1 = exp2f(mM[mt][1] - mn1);
            mM[mt][0] = mn0; mM[mt][1] = mn1;

            float ps0 = 0.f, ps1 = 0.f;
            #pragma unroll
            for (int n = 0; n < 8; n++) {
                sc[mt][n][0] = exp2f(sc[mt][n][0] - mn0);
                sc[mt][n][1] = exp2f(sc[mt][n][1] - mn0);
                sc[mt][n][2] = exp2f(sc[mt][n][2] - mn1);
                sc[mt][n][3] = exp2f(sc[mt][n][3] - mn1);
                ps0 += sc[mt][n][0] + sc[mt][n][1];
                ps1 += sc[mt][n][2] + sc[mt][n][3];
            }
            lL[mt][0] = lL[mt][0] * c0 + ps0;
            lL[mt][1] = lL[mt][1] * c1 + ps1;
            #pragma unroll
            for (int n = 0; n < 8; n++) {
                o[mt][n][0] *= c0; o[mt][n][1] *= c0;
                o[mt][n][2] *= c1; o[mt][n][3] *= c1;
            }
            #pragma unroll
            for (int s = 0; s < 4; s++) {
                __half2 p0 = __floats2half2_rn(sc[mt][2*s][0],   sc[mt][2*s][1]);
                __half2 p1 = __floats2half2_rn(sc[mt][2*s][2],   sc[mt][2*s][3]);
                __half2 p2 = __floats2half2_rn(sc[mt][2*s+1][0], sc[mt][2*s+1][1]);
                __half2 p3 = __floats2half2_rn(sc[mt][2*s+1][2], sc[mt][2*s+1][3]);
                pa[mt][s][0] = *(uint32_t*)&p0;
                pa[mt][s][1] = *(uint32_t*)&p1;
                pa[mt][s][2] = *(uint32_t*)&p2;
                pa[mt][s][3] = *(uint32_t*)&p3;
            }
        }

        // ---- O += P V ----
        #pragma unroll
        for (int s = 0; s < 4; s++) {
            uint32_t vfr[8][2];
            #pragma unroll
            for (int nt = 0; nt < 4; nt++) {
                const int r = s * 16 + (mi & 1) * 8 + (lane & 7);
                const int c = 2 * nt + (mi >> 1);
                ldsm_x4t(vfr[2*nt][0], vfr[2*nt][1], vfr[2*nt+1][0], vfr[2*nt+1][1],
                         vo + r * 128 + ((c ^ (r & 7)) * 16));
            }
            #pragma unroll
            for (int mt = 0; mt < 2; mt++)
                #pragma unroll
                for (int n = 0; n < 8; n++)
                    mma_f16(o[mt][n], pa[mt][s], vfr[n][0], vfr[n][1]);
        }
        __syncthreads();
    }

    // finalize: normalize, split into bf16 hi/lo, store
    #pragma unroll
    for (int mt = 0; mt < 2; mt++) {
        float l0 = lL[mt][0], l1 = lL[mt][1];
        l0 += __shfl_xor_sync(0xffffffffu, l0, 1);
        l0 += __shfl_xor_sync(0xffffffffu, l0, 2);
        l1 += __shfl_xor_sync(0xffffffffu, l1, 1);
        l1 += __shfl_xor_sync(0xffffffffu, l1, 2);
        const float i0 = 1.f / l0, i1 = 1.f / l1;
        const int r0 = wrow + mt * 16 + gg;
        const int r1 = r0 + 8;
        #pragma unroll
        for (int n = 0; n < 8; n++) {
            const int col = h * 64 + n * 8 + tg * 2;
            float v0 = o[mt][n][0] * i0, v1 = o[mt][n][1] * i0;
            float v2 = o[mt][n][2] * i1, v3 = o[mt][n][3] * i1;
            __nv_bfloat162 h0 = __floats2bfloat162_rn(v0, v1);
            __nv_bfloat162 h1 = __floats2bfloat162_rn(v2, v3);
            __nv_bfloat162 e0 = __floats2bfloat162_rn(v0 - __bfloat162float(h0.x),
                                                      v1 - __bfloat162float(h0.y));
            __nv_bfloat162 e1 = __floats2bfloat162_rn(v2 - __bfloat162float(h1.x),
                                                      v3 - __bfloat162float(h1.y));
            *(uint32_t*)(ohi + (size_t)r0 * D_MODEL + col) = *(uint32_t*)&h0;
            *(uint32_t*)(olo + (size_t)r0 * D_MODEL + col) = *(uint32_t*)&e0;
            *(uint32_t*)(ohi + (size_t)r1 * D_MODEL + col) = *(uint32_t*)&h1;
            *(uint32_t*)(olo + (size_t)r1 * D_MODEL + col) = *(uint32_t*)&e1;
        }
    }
}

// ---------------------------------------------------------------------------
// Launch
// ---------------------------------------------------------------------------
extern "C" void kernel_launch(void* const* d_in, const int* in_sizes, int n_in,
                              void* d_out, int out_size)
{
    const float* queries = (const float*)d_in[0];
    const float* keys    = (const float*)d_in[1];
    const float* values  = (const float*)d_in[2];
    const float* Wq      = (const float*)d_in[3];
    const float* bq      = (const float*)d_in[4];
    const float* Wk      = (const float*)d_in[5];
    const float* bk      = (const float*)d_in[6];
    const float* Wv      = (const float*)d_in[7];
    const float* bv      = (const float*)d_in[8];
    const float* Wo      = (const float*)d_in[9];
    const float* bo      = (const float*)d_in[10];
    float*       out     = (float*)d_out;

    __half *qh, *kh, *vh;
    __nv_bfloat16 *ahi, *alo, *bhi, *blo, *chi, *clo;
    __nv_bfloat16 *wqh, *wql, *wkh, *wkl, *wvh, *wvl, *woh, *wol;
    cudaGetSymbolAddress((void**)&qh,  g_qh);
    cudaGetSymbolAddress((void**)&kh,  g_kh);
    cudaGetSymbolAddress((void**)&vh,  g_vh);
    cudaGetSymbolAddress((void**)&ahi, g_ahi);
    cudaGetSymbolAddress((void**)&alo, g_alo);
    cudaGetSymbolAddress((void**)&bhi, g_bhi);
    cudaGetSymbolAddress((void**)&blo, g_blo);
    cudaGetSymbolAddress((void**)&chi, g_chi);
    cudaGetSymbolAddress((void**)&clo, g_clo);
    cudaGetSymbolAddress((void**)&wqh, g_wq_hi);
    cudaGetSymbolAddress((void**)&wql, g_wq_lo);
    cudaGetSymbolAddress((void**)&wkh, g_wk_hi);
    cudaGetSymbolAddress((void**)&wkl, g_wk_lo);
    cudaGetSymbolAddress((void**)&wvh, g_wv_hi);
    cudaGetSymbolAddress((void**)&wvl, g_wv_lo);
    cudaGetSymbolAddress((void**)&woh, g_wo_hi);
    cudaGetSymbolAddress((void**)&wol, g_wo_lo);

    cudaFuncSetAttribute(gemm_one<0>, cudaFuncAttributeMaxDynamicSharedMemorySize, 3 * GSTAGE);
    cudaFuncSetAttribute(gemm_one<2>, cudaFuncAttributeMaxDynamicSharedMemorySize, 3 * GSTAGE);
    cudaFuncSetAttribute(gemm_kv,     cudaFuncAttributeMaxDynamicSharedMemorySize, 3 * GSTAGE);

    const int NELEM4 = S_LEN * D_MODEL / 4;

    // weight prep
    wsplit4<<<dim3(D_MODEL / 32, GK / 32, 4), 256>>>(
        Wq, Wk, Wv, Wo, wqh, wql, wkh, wkl, wvh, wvl, woh, wol);

    // activation splits (all three in one launch)
    asplit3<<<dim3(NELEM4 / 256, 3), 256>>>(
        (const float4*)queries, (const float4*)keys, (const float4*)values,
        ahi, alo, bhi, blo, chi, clo);

    // Q projection (half out, pre-scaled)
    gemm_one<2><<<dim3(D_MODEL / 128, S_LEN / 256), 256, 3 * GSTAGE>>>(
        ahi, alo, wqh, wql, bq, qh, D_MODEL);

    // K + V projections fused (half out)
    gemm_kv<<<dim3(KV_W / 128, S_LEN / 256, 2), 256, 3 * GSTAGE>>>(
        bhi, blo, wkh, wkl, bk, kh,
        chi, clo, wvh, wvl, bv, vh);

    // causal GQA flash attention -> bf16 hi/lo split output
    flash<<<dim3(S_LEN / 128, H_Q), 128>>>(qh, kh, vh, ahi, alo);

    // output projection (float out)
    gemm_one<0><<<dim3(D_MODEL / 128, S_LEN / 256), 256, 3 * GSTAGE>>>(
        ahi, alo, woh, wol, bo, out, D_MODEL);
}

// round 6
// speedup vs baseline: 5.8133x; 1.1486x over previous
#include <cuda_runtime.h>
#include <cuda_bf16.h>
#include <cuda_fp16.h>
#include <cstdint>

// ===========================================================================
// GQA layer, sm_103 baseline-PTX path: mma.sync (HMMA) everywhere.
//   - projections: bf16 split-2 GEMM, CTA tile 128x128 (4 warps, 64x64 each),
//       3-stage cp.async, 2 CTAs/SM, Q+K+V fused into one launch
//   - attention:   fp16 FA-2, q-tile 128/CTA, bf16-split output
// ===========================================================================

#define S_LEN   2048
#define D_MODEL 2048
#define H_Q     32
#define KV_W    512
#define GK      2048
#define QSCALE  0.1803368801111244f   // 0.125 * log2(e)

// ------------------------------ scratch ------------------------------------
__device__ __align__(16) __half g_qh[S_LEN * D_MODEL];
__device__ __align__(16) __half g_kh[S_LEN * KV_W];
__device__ __align__(16) __half g_vh[S_LEN * KV_W];

__device__ __align__(16) __nv_bfloat16 g_ahi[S_LEN * D_MODEL];
__device__ __align__(16) __nv_bfloat16 g_alo[S_LEN * D_MODEL];
__device__ __align__(16) __nv_bfloat16 g_bhi[S_LEN * D_MODEL];
__device__ __align__(16) __nv_bfloat16 g_blo[S_LEN * D_MODEL];
__device__ __align__(16) __nv_bfloat16 g_chi[S_LEN * D_MODEL];
__device__ __align__(16) __nv_bfloat16 g_clo[S_LEN * D_MODEL];

__device__ __align__(16) __nv_bfloat16 g_wq_hi[D_MODEL * GK];
__device__ __align__(16) __nv_bfloat16 g_wq_lo[D_MODEL * GK];
__device__ __align__(16) __nv_bfloat16 g_wk_hi[KV_W * GK];
__device__ __align__(16) __nv_bfloat16 g_wk_lo[KV_W * GK];
__device__ __align__(16) __nv_bfloat16 g_wv_hi[KV_W * GK];
__device__ __align__(16) __nv_bfloat16 g_wv_lo[KV_W * GK];
__device__ __align__(16) __nv_bfloat16 g_wo_hi[D_MODEL * GK];
__device__ __align__(16) __nv_bfloat16 g_wo_lo[D_MODEL * GK];

// ------------------------------ helpers ------------------------------------
__device__ __forceinline__ uint32_t smem_u32(const void* p) {
    uint32_t a;
    asm("{ .reg .u64 t; cvta.to.shared.u64 t, %1; cvt.u32.u64 %0, t; }"
        : "=r"(a) : "l"(p));
    return a;
}

#define CP16(dst, src) \
    asm volatile("cp.async.cg.shared.global [%0], [%1], 16;" \
                 :: "r"(dst), "l"(src))
#define CPCOMMIT() asm volatile("cp.async.commit_group;" ::: "memory")
#define CPWAIT(n)  asm volatile("cp.async.wait_group %0;" :: "n"(n) : "memory")

__device__ __forceinline__ void ldsm_x4(uint32_t& r0, uint32_t& r1,
                                        uint32_t& r2, uint32_t& r3, uint32_t a) {
    asm volatile("ldmatrix.sync.aligned.m8n8.x4.shared.b16 {%0,%1,%2,%3}, [%4];"
                 : "=r"(r0), "=r"(r1), "=r"(r2), "=r"(r3) : "r"(a));
}
__device__ __forceinline__ void ldsm_x4t(uint32_t& r0, uint32_t& r1,
                                         uint32_t& r2, uint32_t& r3, uint32_t a) {
    asm volatile("ldmatrix.sync.aligned.m8n8.x4.trans.shared.b16 {%0,%1,%2,%3}, [%4];"
                 : "=r"(r0), "=r"(r1), "=r"(r2), "=r"(r3) : "r"(a));
}

__device__ __forceinline__ void mma_bf16(float* c, const uint32_t* a,
                                         uint32_t b0, uint32_t b1) {
    asm volatile("mma.sync.aligned.m16n8k16.row.col.f32.bf16.bf16.f32 "
                 "{%0,%1,%2,%3}, {%4,%5,%6,%7}, {%8,%9}, {%0,%1,%2,%3};"
                 : "+f"(c[0]), "+f"(c[1]), "+f"(c[2]), "+f"(c[3])
                 : "r"(a[0]), "r"(a[1]), "r"(a[2]), "r"(a[3]), "r"(b0), "r"(b1));
}
__device__ __forceinline__ void mma_f16(float* c, const uint32_t* a,
                                        uint32_t b0, uint32_t b1) {
    asm volatile("mma.sync.aligned.m16n8k16.row.col.f32.f16.f16.f32 "
                 "{%0,%1,%2,%3}, {%4,%5,%6,%7}, {%8,%9}, {%0,%1,%2,%3};"
                 : "+f"(c[0]), "+f"(c[1]), "+f"(c[2]), "+f"(c[3])
                 : "r"(a[0]), "r"(a[1]), "r"(a[2]), "r"(a[3]), "r"(b0), "r"(b1));
}

// ---------------------------------------------------------------------------
// asplit3: three fp32 activation tensors -> bf16 hi/lo, z-indexed
// ---------------------------------------------------------------------------
__global__ __launch_bounds__(256)
void asplit3(const float4* __restrict__ Q, const float4* __restrict__ K,
             const float4* __restrict__ V,
             __nv_bfloat16* __restrict__ ahi, __nv_bfloat16* __restrict__ alo,
             __nv_bfloat16* __restrict__ bhi, __nv_bfloat16* __restrict__ blo,
             __nv_bfloat16* __restrict__ chi, __nv_bfloat16* __restrict__ clo)
{
    const int z = blockIdx.y;
    const float4* A;  __nv_bfloat16 *hi, *lo;
    if      (z == 0) { A = Q; hi = ahi; lo = alo; }
    else if (z == 1) { A = K; hi = bhi; lo = blo; }
    else             { A = V; hi = chi; lo = clo; }

    const int i = blockIdx.x * 256 + threadIdx.x;
    float4 v = A[i];
    __nv_bfloat162 h0 = __floats2bfloat162_rn(v.x, v.y);
    __nv_bfloat162 h1 = __floats2bfloat162_rn(v.z, v.w);
    __nv_bfloat162 l0 = __floats2bfloat162_rn(v.x - __bfloat162float(h0.x),
                                              v.y - __bfloat162float(h0.y));
    __nv_bfloat162 l1 = __floats2bfloat162_rn(v.z - __bfloat162float(h1.x),
                                              v.w - __bfloat162float(h1.y));
    uint2 uh = make_uint2(*(uint32_t*)&h0, *(uint32_t*)&h1);
    uint2 ul = make_uint2(*(uint32_t*)&l0, *(uint32_t*)&l1);
    *(uint2*)(hi + (size_t)i * 4) = uh;
    *(uint2*)(lo + (size_t)i * 4) = ul;
}

// ---------------------------------------------------------------------------
// wsplit4: all four weights, z-indexed.  W[K,N] fp32 -> hi/lo bf16 [N][K]
// ---------------------------------------------------------------------------
__global__ __launch_bounds__(256)
void wsplit4(const float* __restrict__ Wq, const float* __restrict__ Wk,
             const float* __restrict__ Wv, const float* __restrict__ Wo,
             __nv_bfloat16* __restrict__ qhi, __nv_bfloat16* __restrict__ qlo,
             __nv_bfloat16* __restrict__ khi, __nv_bfloat16* __restrict__ klo,
             __nv_bfloat16* __restrict__ vhi, __nv_bfloat16* __restrict__ vlo,
             __nv_bfloat16* __restrict__ ohi, __nv_bfloat16* __restrict__ olo)
{
    __shared__ float tile[32][33];
    const int z = blockIdx.z;
    const float* W;  __nv_bfloat16 *hi, *lo;  int Ncols;
    if      (z == 0) { W = Wq; hi = qhi; lo = qlo; Ncols = D_MODEL; }
    else if (z == 1) { W = Wk; hi = khi; lo = klo; Ncols = KV_W; }
    else if (z == 2) { W = Wv; hi = vhi; lo = vlo; Ncols = KV_W; }
    else             { W = Wo; hi = ohi; lo = olo; Ncols = D_MODEL; }

    const int bx = blockIdx.x, by = blockIdx.y;
    if (bx * 32 >= Ncols) return;
    const int tx = threadIdx.x & 31, ty = threadIdx.x >> 5;

    #pragma unroll
    for (int i = 0; i < 32; i += 8)
        tile[ty + i][tx] = W[(size_t)(by * 32 + ty + i) * Ncols + bx * 32 + tx];
    __syncthreads();
    #pragma unroll
    for (int i = 0; i < 32; i += 8) {
        const int n = bx * 32 + ty + i;
        const int k = by * 32 + tx;
        float x = tile[tx][ty + i];
        __nv_bfloat16 h = __float2bfloat16_rn(x);
        hi[(size_t)n * GK + k] = h;
        lo[(size_t)n * GK + k] = __float2bfloat16_rn(x - __bfloat162float(h));
    }
}

// ---------------------------------------------------------------------------
// GEMM body: C[128x128 tile] = A @ B^T + bias.  bf16 split-2 (3 passes).
// BK=32, 128 thr, 4 warps (2m x 2n), warp tile 64x64.  3-stage cp.async.
// Stage: Ah(8K) Al(8K) Bh(8K) Bl(8K) = 32KB; 3 stages = 96KB -> 2 CTAs/SM.
// MODE 0: float out; MODE 1: half out; MODE 2: half out * QSCALE.
// ---------------------------------------------------------------------------
#define GSTAGE 32768

template <int MODE>
__device__ __forceinline__
void gemm_body(const __nv_bfloat16* __restrict__ Ahi, const __nv_bfloat16* __restrict__ Alo,
               const __nv_bfloat16* __restrict__ Bhi, const __nv_bfloat16* __restrict__ Blo,
               const float* __restrict__ bias, void* __restrict__ Cout,
               int Ntot, int m0, int n0, uint32_t sb)
{
    const int tid  = threadIdx.x;
    const int lane = tid & 31;
    const int wid  = tid >> 5;
    const int wm   = (wid & 1) * 64;
    const int wn   = (wid >> 1) * 64;
    const int gg   = lane >> 2, tg = lane & 3;
    const int mi   = lane >> 3;

    float acc[4][8][4];
    #pragma unroll
    for (int a = 0; a < 4; a++)
        #pragma unroll
        for (int b = 0; b < 8; b++)
            #pragma unroll
            for (int c = 0; c < 4; c++) acc[a][b][c] = 0.f;

    auto load_stage = [&](int it) {
        const uint32_t st = sb + (it % 3) * GSTAGE;
        const int k0 = it * 32;
        #pragma unroll
        for (int t = 0; t < 4; t++) {
            const int f   = tid + t * 128;
            const int row = f >> 2, c = f & 3;
            const uint32_t sw = row * 64 + ((c ^ ((row >> 1) & 3)) * 16);
            CP16(st + sw,         Ahi + (size_t)(m0 + row) * GK + k0 + c * 8);
            CP16(st + 8192 + sw,  Alo + (size_t)(m0 + row) * GK + k0 + c * 8);
            CP16(st + 16384 + sw, Bhi + (size_t)(n0 + row) * GK + k0 + c * 8);
            CP16(st + 24576 + sw, Blo + (size_t)(n0 + row) * GK + k0 + c * 8);
        }
    };

    load_stage(0); CPCOMMIT();
    load_stage(1); CPCOMMIT();

    const int NIT = GK / 32;
    for (int it = 0; it < NIT; it++) {
        if (it + 1 < NIT) { CPWAIT(1); } else { CPWAIT(0); }
        __syncthreads();
        const uint32_t st = sb + (it % 3) * GSTAGE;

        #pragma unroll
        for (int s = 0; s < 2; s++) {
            uint32_t aH[4][4], aL[4][4];
            #pragma unroll
            for (int mt = 0; mt < 4; mt++) {
                const int r = wm + mt * 16 + (mi & 1) * 8 + (lane & 7);
                const int c = 2 * s + (mi >> 1);
                const uint32_t ad = st + r * 64 + ((c ^ ((r >> 1) & 3)) * 16);
                ldsm_x4(aH[mt][0], aH[mt][1], aH[mt][2], aH[mt][3], ad);
                ldsm_x4(aL[mt][0], aL[mt][1], aL[mt][2], aL[mt][3], ad + 8192);
            }
            uint32_t bH[8][2], bL[8][2];
            #pragma unroll
            for (int nt = 0; nt < 4; nt++) {
                const int r = wn + nt * 16 + (mi >> 1) * 8 + (lane & 7);
                const int c = 2 * s + (mi & 1);
                const uint32_t bd = st + 16384 + r * 64 + ((c ^ ((r >> 1) & 3)) * 16);
                ldsm_x4(bH[2*nt][0], bH[2*nt][1], bH[2*nt+1][0], bH[2*nt+1][1], bd);
                ldsm_x4(bL[2*nt][0], bL[2*nt][1], bL[2*nt+1][0], bL[2*nt+1][1], bd + 8192);
            }
            #pragma unroll
            for (int mt = 0; mt < 4; mt++)
                #pragma unroll
                for (int n = 0; n < 8; n++) {
                    mma_bf16(acc[mt][n], aH[mt], bH[n][0], bH[n][1]);
                    mma_bf16(acc[mt][n], aH[mt], bL[n][0], bL[n][1]);
                    mma_bf16(acc[mt][n], aL[mt], bH[n][0], bH[n][1]);
                }
        }
        if (it + 2 < NIT) { load_stage(it + 2); CPCOMMIT(); }
    }

    #pragma unroll
    for (int mt = 0; mt < 4; mt++)
        #pragma unroll
        for (int n = 0; n < 8; n++) {
            const int r0  = m0 + wm + mt * 16 + gg;
            const int col = n0 + wn + n * 8 + tg * 2;
            const float b0 = bias[col], b1 = bias[col + 1];
            if (MODE == 0) {
                float* C = (float*)Cout;
                *(float2*)(C + (size_t)r0 * Ntot + col) =
                    make_float2(acc[mt][n][0] + b0, acc[mt][n][1] + b1);
                *(float2*)(C + (size_t)(r0 + 8) * Ntot + col) =
                    make_float2(acc[mt][n][2] + b0, acc[mt][n][3] + b1);
            } else {
                const float sc = (MODE == 2) ? QSCALE : 1.0f;
                __half* C = (__half*)Cout;
                __half2 h0 = __floats2half2_rn((acc[mt][n][0] + b0) * sc,
                                               (acc[mt][n][1] + b1) * sc);
                __half2 h1 = __floats2half2_rn((acc[mt][n][2] + b0) * sc,
                                               (acc[mt][n][3] + b1) * sc);
                *(__half2*)(C + (size_t)r0 * Ntot + col) = h0;
                *(__half2*)(C + (size_t)(r0 + 8) * Ntot + col) = h1;
            }
        }
}

// fused Q + K + V projections: grid (24, 16); x<16 -> Q tile, 16-19 K, 20-23 V
__global__ __launch_bounds__(128, 2)
void gemm_qkv(const __nv_bfloat16* __restrict__ Qhi, const __nv_bfloat16* __restrict__ Qlo,
              const __nv_bfloat16* __restrict__ Khi, const __nv_bfloat16* __restrict__ Klo,
              const __nv_bfloat16* __restrict__ Vhi, const __nv_bfloat16* __restrict__ Vlo,
              const __nv_bfloat16* __restrict__ WQhi, const __nv_bfloat16* __restrict__ WQlo,
              const __nv_bfloat16* __restrict__ WKhi, const __nv_bfloat16* __restrict__ WKlo,
              const __nv_bfloat16* __restrict__ WVhi, const __nv_bfloat16* __restrict__ WVlo,
              const float* __restrict__ bq, const float* __restrict__ bk,
              const float* __restrict__ bv,
              __half* __restrict__ qh, __half* __restrict__ kh, __half* __restrict__ vh)
{
    extern __shared__ char sm[];
    const uint32_t sb = smem_u32(sm);
    const int bx = blockIdx.x;
    const int m0 = blockIdx.y * 128;
    if (bx < 16)
        gemm_body<2>(Qhi, Qlo, WQhi, WQlo, bq, qh, D_MODEL, m0, bx * 128, sb);
    else if (bx < 20)
        gemm_body<1>(Khi, Klo, WKhi, WKlo, bk, kh, KV_W, m0, (bx - 16) * 128, sb);
    else
        gemm_body<1>(Vhi, Vlo, WVhi, WVlo, bv, vh, KV_W, m0, (bx - 20) * 128, sb);
}

// output projection
__global__ __launch_bounds__(128, 2)
void gemm_o(const __nv_bfloat16* __restrict__ Ahi, const __nv_bfloat16* __restrict__ Alo,
            const __nv_bfloat16* __restrict__ Bhi, const __nv_bfloat16* __restrict__ Blo,
            const float* __restrict__ bias, float* __restrict__ Cout)
{
    extern __shared__ char sm[];
    gemm_body<0>(Ahi, Alo, Bhi, Blo, bias, Cout, D_MODEL,
                 blockIdx.y * 128, blockIdx.x * 128, smem_u32(sm));
}

// ---------------------------------------------------------------------------
// fp16 HMMA causal flash attention.  q-tile 128/CTA, 4 warps (32 q-rows each),
// kv tile 64, double-buffered.  Output written as bf16 hi/lo split.
// ---------------------------------------------------------------------------
__global__ __launch_bounds__(128)
void flash(const __half* __restrict__ qbuf, const __half* __restrict__ kbuf,
           const __half* __restrict__ vbuf,
           __nv_bfloat16* __restrict__ ohi, __nv_bfloat16* __restrict__ olo)
{
    __shared__ __align__(16) __half sQ[128 * 64];
    __shared__ __align__(16) __half sK[2][64 * 64];
    __shared__ __align__(16) __half sV[2][64 * 64];

    const int qt   = (int)gridDim.x - 1 - (int)blockIdx.x;
    const int h    = blockIdx.y;
    const int g    = h >> 2;
    const int tid  = threadIdx.x;
    const int warp = tid >> 5, lane = tid & 31;
    const int gg   = lane >> 2, tg = lane & 3;
    const int mi   = lane >> 3;
    const int q0   = qt * 128;
    const int wrow = q0 + warp * 32;

    const uint32_t qb  = smem_u32(sQ);
    const uint32_t kb0 = smem_u32(sK);
    const uint32_t vb0 = smem_u32(sV);

    #pragma unroll
    for (int i = 0; i < 8; i++) {
        const int f = tid + i * 128;
        const int r = f >> 3, c = f & 7;
        CP16(qb + r * 128 + ((c ^ (r & 7)) * 16),
             qbuf + (size_t)(q0 + r) * D_MODEL + h * 64 + c * 8);
    }
    auto loadKV = [&](int kt) {
        const uint32_t ko = kb0 + (kt & 1) * 8192;
        const uint32_t vo = vb0 + (kt & 1) * 8192;
        #pragma unroll
        for (int i = 0; i < 4; i++) {
            const int f = tid + i * 128;
            const int r = f >> 3, c = f & 7;
            const size_t src = (size_t)(kt * 64 + r) * KV_W + g * 64 + c * 8;
            const uint32_t d = r * 128 + ((c ^ (r & 7)) * 16);
            CP16(ko + d, kbuf + src);
            CP16(vo + d, vbuf + src);
        }
    };
    loadKV(0);
    CPCOMMIT();
    CPWAIT(0);
    __syncthreads();

    uint32_t qa[4][2][4];
    #pragma unroll
    for (int mt = 0; mt < 2; mt++) {
        const int r = warp * 32 + mt * 16 + (mi & 1) * 8 + (lane & 7);
        #pragma unroll
        for (int s = 0; s < 4; s++) {
            const int c = 2 * s + (mi >> 1);
            ldsm_x4(qa[s][mt][0], qa[s][mt][1], qa[s][mt][2], qa[s][mt][3],
                    qb + r * 128 + ((c ^ (r & 7)) * 16));
        }
    }

    float o[2][8][4];
    #pragma unroll
    for (int mt = 0; mt < 2; mt++)
        #pragma unroll
        for (int n = 0; n < 8; n++)
            #pragma unroll
            for (int c = 0; c < 4; c++) o[mt][n][c] = 0.f;
    float mM[2][2] = {{-1e30f, -1e30f}, {-1e30f, -1e30f}};
    float lL[2][2] = {{0.f, 0.f}, {0.f, 0.f}};

    const int KT = 2 * qt + 2;
    for (int kt = 0; kt < KT; kt++) {
        if (kt + 1 < KT) { loadKV(kt + 1); CPCOMMIT(); CPWAIT(1); }
        else             { CPWAIT(0); }
        __syncthreads();
        const uint32_t ko = kb0 + (kt & 1) * 8192;
        const uint32_t vo = vb0 + (kt & 1) * 8192;

        float sc[2][8][4];
        #pragma unroll
        for (int mt = 0; mt < 2; mt++)
            #pragma unroll
            for (int n = 0; n < 8; n++)
                #pragma unroll
                for (int c = 0; c < 4; c++) sc[mt][n][c] = 0.f;

        #pragma unroll
        for (int s = 0; s < 4; s++) {
            uint32_t bfr[8][2];
            #pragma unroll
            for (int nt = 0; nt < 4; nt++) {
                const int r = nt * 16 + (mi >> 1) * 8 + (lane & 7);
                const int c = 2 * s + (mi & 1);
                ldsm_x4(bfr[2*nt][0], bfr[2*nt][1], bfr[2*nt+1][0], bfr[2*nt+1][1],
                        ko + r * 128 + ((c ^ (r & 7)) * 16));
            }
            #pragma unroll
            for (int mt = 0; mt < 2; mt++)
                #pragma unroll
                for (int n = 0; n < 8; n++)
                    mma_f16(sc[mt][n], qa[s][mt], bfr[n][0], bfr[n][1]);
        }

        if (kt * 64 + 63 > wrow) {
            #pragma unroll
            for (int mt = 0; mt < 2; mt++) {
                const int r0 = wrow + mt * 16 + gg;
                const int r1 = r0 + 8;
                #pragma unroll
                for (int n = 0; n < 8; n++) {
                    const int col = kt * 64 + n * 8 + tg * 2;
                    if (col     > r0) sc[mt][n][0] = -1e30f;
                    if (col + 1 > r0) sc[mt][n][1] = -1e30f;
                    if (col     > r1) sc[mt][n][2] = -1e30f;
                    if (col + 1 > r1) sc[mt][n][3] = -1e30f;
                }
            }
        }

        uint32_t pa[2][4][4];
        #pragma unroll
        for (int mt = 0; mt < 2; mt++) {
            float mx0 = -1e30f, mx1 = -1e30f;
            #pragma unroll
            for (int n = 0; n < 8; n++) {
                mx0 = fmaxf(mx0, fmaxf(sc[mt][n][0], sc[mt][n][1]));
                mx1 = fmaxf(mx1, fmaxf(sc[mt][n][2], sc[mt][n][3]));
            }
            mx0 = fmaxf(mx0, __shfl_xor_sync(0xffffffffu, mx0, 1));
            mx0 = fmaxf(mx0, __shfl_xor_sync(0xffffffffu, mx0, 2));
            mx1 = fmaxf(mx1, __shfl_xor_sync(0xffffffffu, mx1, 1));
            mx1 = fmaxf(mx1, __shfl_xor_sync(0xffffffffu, mx1, 2));
            const float mn0 = fmaxf(mM[mt][0], mx0);
            const float mn1 = fmaxf(mM[mt][1], mx1);
            const float c0 = exp2f(mM[mt][0] - mn0);
            const float c1 = exp2f(mM[mt][1] - mn1);
            mM[mt][0] = mn0; mM[mt][1] = mn1;

            float ps0 = 0.f, ps1 = 0.f;
            #pragma unroll
            for (int n = 0; n < 8; n++) {
                sc[mt][n][0] = exp2f(sc[mt][n][0] - mn0);
                sc[mt][n][1] = exp2f(sc[mt][n][1] - mn0);
                sc[mt][n][2] = exp2f(sc[mt][n][2] - mn1);
                sc[mt][n][3] = exp2f(sc[mt][n][3] - mn1);
                ps0 += sc[mt][n][0] + sc[mt][n][1];
                ps1 += sc[mt][n][2] + sc[mt][n][3];
            }
            lL[mt][0] = lL[mt][0] * c0 + ps0;
            lL[mt][1] = lL[mt][1] * c1 + ps1;
            #pragma unroll
            for (int n = 0; n < 8; n++) {
                o[mt][n][0] *= c0; o[mt][n][1] *= c0;
                o[mt][n][2] *= c1; o[mt][n][3] *= c1;
            }
            #pragma unroll
            for (int s = 0; s < 4; s++) {
                __half2 p0 = __floats2half2_rn(sc[mt][2*s][0],   sc[mt][2*s][1]);
                __half2 p1 = __floats2half2_rn(sc[mt][2*s][2],   sc[mt][2*s][3]);
                __half2 p2 = __floats2half2_rn(sc[mt][2*s+1][0], sc[mt][2*s+1][1]);
                __half2 p3 = __floats2half2_rn(sc[mt][2*s+1][2], sc[mt][2*s+1][3]);
                pa[mt][s][0] = *(uint32_t*)&p0;
                pa[mt][s][1] = *(uint32_t*)&p1;
                pa[mt][s][2] = *(uint32_t*)&p2;
                pa[mt][s][3] = *(uint32_t*)&p3;
            }
        }

        #pragma unroll
        for (int s = 0; s < 4; s++) {
            uint32_t vfr[8][2];
            #pragma unroll
            for (int nt = 0; nt < 4; nt++) {
                const int r = s * 16 + (mi & 1) * 8 + (lane & 7);
                const int c = 2 * nt + (mi >> 1);
                ldsm_x4t(vfr[2*nt][0], vfr[2*nt][1], vfr[2*nt+1][0], vfr[2*nt+1][1],
                         vo + r * 128 + ((c ^ (r & 7)) * 16));
            }
            #pragma unroll
            for (int mt = 0; mt < 2; mt++)
                #pragma unroll
                for (int n = 0; n < 8; n++)
                    mma_f16(o[mt][n], pa[mt][s], vfr[n][0], vfr[n][1]);
        }
        __syncthreads();
    }

    #pragma unroll
    for (int mt = 0; mt < 2; mt++) {
        float l0 = lL[mt][0], l1 = lL[mt][1];
        l0 += __shfl_xor_sync(0xffffffffu, l0, 1);
        l0 += __shfl_xor_sync(0xffffffffu, l0, 2);
        l1 += __shfl_xor_sync(0xffffffffu, l1, 1);
        l1 += __shfl_xor_sync(0xffffffffu, l1, 2);
        const float i0 = 1.f / l0, i1 = 1.f / l1;
        const int r0 = wrow + mt * 16 + gg;
        const int r1 = r0 + 8;
        #pragma unroll
        for (int n = 0; n < 8; n++) {
            const int col = h * 64 + n * 8 + tg * 2;
            float v0 = o[mt][n][0] * i0, v1 = o[mt][n][1] * i0;
            float v2 = o[mt][n][2] * i1, v3 = o[mt][n][3] * i1;
            __nv_bfloat162 h0 = __floats2bfloat162_rn(v0, v1);
            __nv_bfloat162 h1 = __floats2bfloat162_rn(v2, v3);
            __nv_bfloat162 e0 = __floats2bfloat162_rn(v0 - __bfloat162float(h0.x),
                                                      v1 - __bfloat162float(h0.y));
            __nv_bfloat162 e1 = __floats2bfloat162_rn(v2 - __bfloat162float(h1.x),
                                                      v3 - __bfloat162float(h1.y));
            *(uint32_t*)(ohi + (size_t)r0 * D_MODEL + col) = *(uint32_t*)&h0;
            *(uint32_t*)(olo + (size_t)r0 * D_MODEL + col) = *(uint32_t*)&e0;
            *(uint32_t*)(ohi + (size_t)r1 * D_MODEL + col) = *(uint32_t*)&h1;
            *(uint32_t*)(olo + (size_t)r1 * D_MODEL + col) = *(uint32_t*)&e1;
        }
    }
}

// ---------------------------------------------------------------------------
// Launch
// ---------------------------------------------------------------------------
extern "C" void kernel_launch(void* const* d_in, const int* in_sizes, int n_in,
                              void* d_out, int out_size)
{
    const float* queries = (const float*)d_in[0];
    const float* keys    = (const float*)d_in[1];
    const float* values  = (const float*)d_in[2];
    const float* Wq      = (const float*)d_in[3];
    const float* bq      = (const float*)d_in[4];
    const float* Wk      = (const float*)d_in[5];
    const float* bk      = (const float*)d_in[6];
    const float* Wv      = (const float*)d_in[7];
    const float* bv      = (const float*)d_in[8];
    const float* Wo      = (const float*)d_in[9];
    const float* bo      = (const float*)d_in[10];
    float*       out     = (float*)d_out;

    __half *qh, *kh, *vh;
    __nv_bfloat16 *ahi, *alo, *bhi, *blo, *chi, *clo;
    __nv_bfloat16 *wqh, *wql, *wkh, *wkl, *wvh, *wvl, *woh, *wol;
    cudaGetSymbolAddress((void**)&qh,  g_qh);
    cudaGetSymbolAddress((void**)&kh,  g_kh);
    cudaGetSymbolAddress((void**)&vh,  g_vh);
    cudaGetSymbolAddress((void**)&ahi, g_ahi);
    cudaGetSymbolAddress((void**)&alo, g_alo);
    cudaGetSymbolAddress((void**)&bhi, g_bhi);
    cudaGetSymbolAddress((void**)&blo, g_blo);
    cudaGetSymbolAddress((void**)&chi, g_chi);
    cudaGetSymbolAddress((void**)&clo, g_clo);
    cudaGetSymbolAddress((void**)&wqh, g_wq_hi);
    cudaGetSymbolAddress((void**)&wql, g_wq_lo);
    cudaGetSymbolAddress((void**)&wkh, g_wk_hi);
    cudaGetSymbolAddress((void**)&wkl, g_wk_lo);
    cudaGetSymbolAddress((void**)&wvh, g_wv_hi);
    cudaGetSymbolAddress((void**)&wvl, g_wv_lo);
    cudaGetSymbolAddress((void**)&woh, g_wo_hi);
    cudaGetSymbolAddress((void**)&wol, g_wo_lo);

    cudaFuncSetAttribute(gemm_qkv, cudaFuncAttributeMaxDynamicSharedMemorySize, 3 * GSTAGE);
    cudaFuncSetAttribute(gemm_o,   cudaFuncAttributeMaxDynamicSharedMemorySize, 3 * GSTAGE);

    const int NELEM4 = S_LEN * D_MODEL / 4;

    // weight prep
    wsplit4<<<dim3(D_MODEL / 32, GK / 32, 4), 256>>>(
        Wq, Wk, Wv, Wo, wqh, wql, wkh, wkl, wvh, wvl, woh, wol);

    // activation splits
    asplit3<<<dim3(NELEM4 / 256, 3), 256>>>(
        (const float4*)queries, (const float4*)keys, (const float4*)values,
        ahi, alo, bhi, blo, chi, clo);

    // Q + K + V projections fused: grid (24, 16) = 384 CTAs, 2 per SM
    gemm_qkv<<<dim3(24, S_LEN / 128), 128, 3 * GSTAGE>>>(
        ahi, alo, bhi, blo, chi, clo,
        wqh, wql, wkh, wkl, wvh, wvl,
        bq, bk, bv, qh, kh, vh);

    // causal GQA flash attention -> bf16 hi/lo split output
    flash<<<dim3(S_LEN / 128, H_Q), 128>>>(qh, kh, vh, ahi, alo);

    // output projection
    gemm_o<<<dim3(D_MODEL / 128, S_LEN / 128), 128, 3 * GSTAGE>>>(
        ahi, alo, woh, wol, bo, out);
}